// round 8
// baseline (speedup 1.0000x reference)
#include <cuda_runtime.h>
#include <cuda_bf16.h>
#include <math.h>
#include <cstdint>

#define SEQ   2048
#define DIM   4096
#define NH    32
#define NKV   8
#define HD    128
#define KVD   (NKV * HD)             /* 1024 */
#define QKV_W (DIM + 2 * KVD)        /* 6144: [q 4096 | k 1024 | v 1024] per row */

// ---------------------------------------------------------------------------
// Scratch (__device__ globals — the sanctioned allocation mechanism)
// ---------------------------------------------------------------------------
__device__ float g_qkv[SEQ * QKV_W];
__device__ __nv_bfloat16 g_xh[SEQ * DIM],    g_xl[SEQ * DIM];
__device__ __nv_bfloat16 g_wAh[QKV_W * DIM], g_wAl[QKV_W * DIM];  // wq|wk|wv fused
__device__ __nv_bfloat16 g_woh[DIM * DIM],   g_wol[DIM * DIM];
__device__ __nv_bfloat16 g_ah[SEQ * DIM],    g_al[SEQ * DIM];     // flash output (split)

// ---------------------------------------------------------------------------
// helpers
// ---------------------------------------------------------------------------
__device__ __forceinline__ uint32_t smem_u32(const void* p) {
    uint32_t a;
    asm("{ .reg .u64 t; cvta.to.shared.u64 t, %1; cvt.u32.u64 %0, t; }"
        : "=r"(a) : "l"(p));
    return a;
}
__device__ __forceinline__ void cp_async16(uint32_t dst, const void* src) {
    asm volatile("cp.async.cg.shared.global [%0], [%1], 16;"
                 :: "r"(dst), "l"(src));
}
// NOTE: no volatile — pure register op; lets the scheduler interleave MMAs.
__device__ __forceinline__ void mma_bf16(float& d0, float& d1, float& d2, float& d3,
                                         uint32_t a0, uint32_t a1, uint32_t a2, uint32_t a3,
                                         uint32_t b0, uint32_t b1)
{
    asm("mma.sync.aligned.m16n8k16.row.col.f32.bf16.bf16.f32 "
        "{%0,%1,%2,%3}, {%4,%5,%6,%7}, {%8,%9}, {%0,%1,%2,%3};"
        : "+f"(d0), "+f"(d1), "+f"(d2), "+f"(d3)
        : "r"(a0), "r"(a1), "r"(a2), "r"(a3), "r"(b0), "r"(b1));
}
__device__ __forceinline__ void ldsm4(uint32_t& r0, uint32_t& r1, uint32_t& r2,
                                      uint32_t& r3, uint32_t a)
{
    asm volatile("ldmatrix.sync.aligned.m8n8.x4.shared.b16 {%0,%1,%2,%3}, [%4];"
                 : "=r"(r0), "=r"(r1), "=r"(r2), "=r"(r3) : "r"(a));
}
__device__ __forceinline__ void ldsm4t(uint32_t& r0, uint32_t& r1, uint32_t& r2,
                                       uint32_t& r3, uint32_t a)
{
    asm volatile("ldmatrix.sync.aligned.m8n8.x4.trans.shared.b16 {%0,%1,%2,%3}, [%4];"
                 : "=r"(r0), "=r"(r1), "=r"(r2), "=r"(r3) : "r"(a));
}
__device__ __forceinline__ void split4(float4 v, uint2& h, uint2& l) {
    __nv_bfloat16 h0 = __float2bfloat16(v.x), h1 = __float2bfloat16(v.y);
    __nv_bfloat16 h2 = __float2bfloat16(v.z), h3 = __float2bfloat16(v.w);
    __nv_bfloat162 ha(h0, h1), hb(h2, h3);
    __nv_bfloat162 la(__float2bfloat16(v.x - __bfloat162float(h0)),
                      __float2bfloat16(v.y - __bfloat162float(h1)));
    __nv_bfloat162 lb(__float2bfloat16(v.z - __bfloat162float(h2)),
                      __float2bfloat16(v.w - __bfloat162float(h3)));
    h = make_uint2(*(uint32_t*)&ha, *(uint32_t*)&hb);
    l = make_uint2(*(uint32_t*)&la, *(uint32_t*)&lb);
}
__device__ __forceinline__ void split2(float x, float y, uint32_t& h, uint32_t& l) {
    __nv_bfloat16 hx = __float2bfloat16(x), hy = __float2bfloat16(y);
    __nv_bfloat162 hv(hx, hy);
    __nv_bfloat162 lv(__float2bfloat16(x - __bfloat162float(hx)),
                      __float2bfloat16(y - __bfloat162float(hy)));
    h = *(uint32_t*)&hv;
    l = *(uint32_t*)&lv;
}

// ---------------------------------------------------------------------------
// fp32 -> bf16 hi/lo split (vectorized x4)
// ---------------------------------------------------------------------------
__global__ void split_kernel(const float* __restrict__ src,
                             __nv_bfloat16* __restrict__ hi,
                             __nv_bfloat16* __restrict__ lo, int n4)
{
    int i = blockIdx.x * blockDim.x + threadIdx.x;
    if (i >= n4) return;
    float4 v = ((const float4*)src)[i];
    uint2 h, l;
    split4(v, h, l);
    ((uint2*)hi)[i] = h;
    ((uint2*)lo)[i] = l;
}

// ---------------------------------------------------------------------------
// HMMA GEMM: C[M,N] = A[M,K] * B[N,K]^T, bf16x3 split, fp32 accum.
// 128x256 tile, warp 64x64 (2x4), BK=32, 4-stage cp.async, XOR swizzle.
// Inner loop is TERM-MAJOR: each accumulator's 3 split terms are 32 MMAs
// apart (no RAW back-to-back chains).
// ---------------------------------------------------------------------------
#define AH3   0
#define AL3   (128 * 32)
#define BH3   (2 * 128 * 32)
#define BL3   (BH3 + 256 * 32)
#define STG3  (BH3 + 2 * 256 * 32)       /* 24576 halfs = 49152 B */
#define GEMM_SMEM (4 * STG3 * 2)         /* 196608 B */

__global__ void __launch_bounds__(256, 1) gemm_mma2(
    const __nv_bfloat16* __restrict__ Ah, const __nv_bfloat16* __restrict__ Al,
    const __nv_bfloat16* __restrict__ Bh, const __nv_bfloat16* __restrict__ Bl,
    float* __restrict__ C, int ldc, int K)
{
    extern __shared__ __nv_bfloat16 sm3[];
    const uint32_t sbase = smem_u32(sm3);
    const int tid = threadIdx.x;
    const int wid = tid >> 5, lane = tid & 31;
    const int warp_m = wid & 1, warp_n = wid >> 1;
    const int g = lane >> 2, t = lane & 3;
    const int m0 = blockIdx.y * 128, n0 = blockIdx.x * 256;

    const int rl = lane & 15;
    const int sw = (rl >> 1) & 3;
    const int ch = lane >> 4;
    const uint32_t LM0 = rl * 32 + (((ch + 0) ^ sw) << 3);
    const uint32_t LM1 = rl * 32 + (((ch + 2) ^ sw) << 3);

    const __nv_bfloat16* gAh = Ah + (size_t)m0 * K;
    const __nv_bfloat16* gAl = Al + (size_t)m0 * K;
    const __nv_bfloat16* gBh = Bh + (size_t)n0 * K;
    const __nv_bfloat16* gBl = Bl + (size_t)n0 * K;

    float d[4][8][4];
#pragma unroll
    for (int i = 0; i < 4; i++)
#pragma unroll
        for (int j = 0; j < 8; j++)
#pragma unroll
            for (int e = 0; e < 4; e++) d[i][j][e] = 0.f;

    const int nk = K / 32;

    auto issue = [&](int s, int buf) {
        const int koff = s * 32;
        const uint32_t stg = sbase + (uint32_t)buf * (STG3 * 2);
#pragma unroll
        for (int j = 0; j < 12; j++) {
            int idx = tid + j * 256;
            const __nv_bfloat16* src;
            uint32_t off;
            int r;
            if (idx < 512)       { r = idx >> 2;          src = gAh; off = AH3; }
            else if (idx < 1024) { r = (idx - 512) >> 2;  src = gAl; off = AL3; }
            else if (idx < 2048) { r = (idx - 1024) >> 2; src = gBh; off = BH3; }
            else                 { r = (idx - 2048) >> 2; src = gBl; off = BL3; }
            int c = idx & 3;
            int cs = c ^ ((r >> 1) & 3);
            cp_async16(stg + 2 * (off + r * 32 + cs * 8),
                       src + (size_t)r * K + koff + c * 8);
        }
        asm volatile("cp.async.commit_group;" ::: "memory");
    };

    issue(0, 0);
    if (nk > 1) issue(1, 1);
    if (nk > 2) issue(2, 2);

    for (int s = 0; s < nk; s++) {
        const int buf = s & 3;
        if (s + 2 < nk)      asm volatile("cp.async.wait_group 2;" ::: "memory");
        else if (s + 1 < nk) asm volatile("cp.async.wait_group 1;" ::: "memory");
        else                 asm volatile("cp.async.wait_group 0;" ::: "memory");
        __syncthreads();     // single barrier per stage (ring-ordering argument)
        if (s + 3 < nk) issue(s + 3, (s + 3) & 3);

        const uint32_t stg = sbase + (uint32_t)buf * (STG3 * 2);

#pragma unroll
        for (int ks = 0; ks < 2; ks++) {
            const uint32_t LM = ks ? LM1 : LM0;
            uint32_t aH[4][4], aL[4][4], bH[4][4], bL[4][4];
#pragma unroll
            for (int mt = 0; mt < 4; mt++) {
                uint32_t ab = stg + 2 * ((warp_m * 64 + mt * 16) * 32 + LM);
                ldsm4(aH[mt][0], aH[mt][1], aH[mt][2], aH[mt][3], ab + 2 * AH3);
                ldsm4(aL[mt][0], aL[mt][1], aL[mt][2], aL[mt][3], ab + 2 * AL3);
            }
#pragma unroll
            for (int ng = 0; ng < 4; ng++) {
                uint32_t bb = stg + 2 * ((warp_n * 64 + ng * 16) * 32 + LM);
                ldsm4(bH[ng][0], bH[ng][1], bH[ng][2], bH[ng][3], bb + 2 * BH3);
                ldsm4(bL[ng][0], bL[ng][1], bL[ng][2], bL[ng][3], bb + 2 * BL3);
            }
            // term 1: Ah * Bh
#pragma unroll
            for (int ng = 0; ng < 4; ng++)
#pragma unroll
                for (int mt = 0; mt < 4; mt++) {
                    mma_bf16(d[mt][2*ng][0], d[mt][2*ng][1], d[mt][2*ng][2], d[mt][2*ng][3],
                             aH[mt][0], aH[mt][1], aH[mt][2], aH[mt][3], bH[ng][0], bH[ng][2]);
                    mma_bf16(d[mt][2*ng+1][0], d[mt][2*ng+1][1], d[mt][2*ng+1][2], d[mt][2*ng+1][3],
                             aH[mt][0], aH[mt][1], aH[mt][2], aH[mt][3], bH[ng][1], bH[ng][3]);
                }
            // term 2: Ah * Bl
#pragma unroll
            for (int ng = 0; ng < 4; ng++)
#pragma unroll
                for (int mt = 0; mt < 4; mt++) {
                    mma_bf16(d[mt][2*ng][0], d[mt][2*ng][1], d[mt][2*ng][2], d[mt][2*ng][3],
                             aH[mt][0], aH[mt][1], aH[mt][2], aH[mt][3], bL[ng][0], bL[ng][2]);
                    mma_bf16(d[mt][2*ng+1][0], d[mt][2*ng+1][1], d[mt][2*ng+1][2], d[mt][2*ng+1][3],
                             aH[mt][0], aH[mt][1], aH[mt][2], aH[mt][3], bL[ng][1], bL[ng][3]);
                }
            // term 3: Al * Bh
#pragma unroll
            for (int ng = 0; ng < 4; ng++)
#pragma unroll
                for (int mt = 0; mt < 4; mt++) {
                    mma_bf16(d[mt][2*ng][0], d[mt][2*ng][1], d[mt][2*ng][2], d[mt][2*ng][3],
                             aL[mt][0], aL[mt][1], aL[mt][2], aL[mt][3], bH[ng][0], bH[ng][2]);
                    mma_bf16(d[mt][2*ng+1][0], d[mt][2*ng+1][1], d[mt][2*ng+1][2], d[mt][2*ng+1][3],
                             aL[mt][0], aL[mt][1], aL[mt][2], aL[mt][3], bH[ng][1], bH[ng][3]);
                }
        }
    }
    __syncthreads();

    // epilogue
#pragma unroll
    for (int mt = 0; mt < 4; mt++) {
        const int row = m0 + warp_m * 64 + mt * 16 + g;
#pragma unroll
        for (int nt = 0; nt < 8; nt++) {
            const int col = n0 + warp_n * 64 + nt * 8 + 2 * t;
            *(float2*)(C + (size_t)row * ldc + col) =
                make_float2(d[mt][nt][0], d[mt][nt][1]);
            *(float2*)(C + (size_t)(row + 8) * ldc + col) =
                make_float2(d[mt][nt][2], d[mt][nt][3]);
        }
    }
}

// ---------------------------------------------------------------------------
// RoPE in-place on Q (heads 0..31) and K (heads 32..39) inside g_qkv.
// ---------------------------------------------------------------------------
__global__ void rope_kernel(const float* __restrict__ cosb,
                            const float* __restrict__ sinb)
{
    int idx = blockIdx.x * blockDim.x + threadIdx.x;
    int p = idx & 63;
    int h = (idx >> 6) % 40;
    int s = idx / (64 * 40);
    float c  = cosb[s * 64 + p];
    float sn = sinb[s * 64 + p];
    float* base = g_qkv + (size_t)s * QKV_W
                + (h < NH ? h * HD : DIM + (h - NH) * HD) + 2 * p;
    float re = base[0], im = base[1];
    base[0] = re * c - im * sn;
    base[1] = re * sn + im * c;
}

// ---------------------------------------------------------------------------
// Tensor-core flash attention.  Block = 128 q x 1 head, 8 warps x 16 rows.
// QK^T and PV via mma.sync bf16x3 (term-major, no RAW chains), P in regs.
// Output written directly as bf16 hi/lo split (g_ah / g_al).
// ---------------------------------------------------------------------------
#define FS    136
#define QHO   0
#define QLO   17408
#define KHO   34816
#define KLO   43520
#define VHO   52224
#define VLO   60928
#define FLASH_SMEM2 (69632 * 2)

__global__ void __launch_bounds__(256, 1) flash_mma()
{
    extern __shared__ __nv_bfloat16 sb[];
    const uint32_t sb2 = smem_u32(sb);
    const int qt = blockIdx.x, h = blockIdx.y;
    const int q0 = qt * 128;
    const int kvh = h >> 2;
    const int tid = threadIdx.x;
    const int wid = tid >> 5, lane = tid & 31;
    const int g = lane >> 2, t = lane & 3;
    const int rmin = q0 + wid * 16;
    const uint32_t LM = (lane & 15) * FS + ((lane >> 4) << 3);

    const float* qb = g_qkv + (size_t)q0 * QKV_W + h * HD;
#pragma unroll
    for (int p = 0; p < 16; p++) {
        int i = tid + p * 256;
        int r = i >> 5, c4 = i & 31;
        float4 v = *(const float4*)(qb + (size_t)r * QKV_W + c4 * 4);
        uint2 hh, ll;
        split4(v, hh, ll);
        int o = r * FS + c4 * 4;
        *(uint2*)&sb[QHO + o] = hh;
        *(uint2*)&sb[QLO + o] = ll;
    }

    float m0 = -1e30f, m1 = -1e30f, l0 = 0.f, l1 = 0.f;
    float o[16][4];
#pragma unroll
    for (int i = 0; i < 16; i++)
#pragma unroll
        for (int e = 0; e < 4; e++) o[i][e] = 0.f;

    const float scale = 0.08838834764831845f;
    const int nkt = 2 * (qt + 1);

    for (int kt = 0; kt < nkt; kt++) {
        __syncthreads();
        const float* kb = g_qkv + (size_t)(kt * 64) * QKV_W + DIM + kvh * HD;
        const float* vb = kb + KVD;
#pragma unroll
        for (int p = 0; p < 8; p++) {
            int i = tid + p * 256;
            int r = i >> 5, c4 = i & 31;
            int o2 = r * FS + c4 * 4;
            float4 kv = *(const float4*)(kb + (size_t)r * QKV_W + c4 * 4);
            uint2 hh, ll;
            split4(kv, hh, ll);
            *(uint2*)&sb[KHO + o2] = hh;
            *(uint2*)&sb[KLO + o2] = ll;
            float4 vv = *(const float4*)(vb + (size_t)r * QKV_W + c4 * 4);
            split4(vv, hh, ll);
            *(uint2*)&sb[VHO + o2] = hh;
            *(uint2*)&sb[VLO + o2] = ll;
        }
        __syncthreads();

        if (kt * 64 > rmin + 15) continue;

        float s[8][4];
#pragma unroll
        for (int i = 0; i < 8; i++)
#pragma unroll
            for (int e = 0; e < 4; e++) s[i][e] = 0.f;

#pragma unroll
        for (int ks = 0; ks < 8; ks++) {
            uint32_t qa = sb2 + 2 * (QHO + wid * 16 * FS + LM + ks * 16);
            uint32_t qh0, qh1, qh2, qh3, ql0, ql1, ql2, ql3;
            ldsm4(qh0, qh1, qh2, qh3, qa);
            ldsm4(ql0, ql1, ql2, ql3, qa + 2 * (QLO - QHO));
            uint32_t kh[4][4], kl[4][4];
#pragma unroll
            for (int np = 0; np < 4; np++) {
                uint32_t ka = sb2 + 2 * (KHO + np * 16 * FS + LM + ks * 16);
                ldsm4(kh[np][0], kh[np][1], kh[np][2], kh[np][3], ka);
                ldsm4(kl[np][0], kl[np][1], kl[np][2], kl[np][3], ka + 2 * (KLO - KHO));
            }
            // term-major: 8 independent MMAs between accumulator reuses
#pragma unroll
            for (int np = 0; np < 4; np++) {
                mma_bf16(s[2*np][0], s[2*np][1], s[2*np][2], s[2*np][3],
                         qh0, qh1, qh2, qh3, kh[np][0], kh[np][2]);
                mma_bf16(s[2*np+1][0], s[2*np+1][1], s[2*np+1][2], s[2*np+1][3],
                         qh0, qh1, qh2, qh3, kh[np][1], kh[np][3]);
            }
#pragma unroll
            for (int np = 0; np < 4; np++) {
                mma_bf16(s[2*np][0], s[2*np][1], s[2*np][2], s[2*np][3],
                         qh0, qh1, qh2, qh3, kl[np][0], kl[np][2]);
                mma_bf16(s[2*np+1][0], s[2*np+1][1], s[2*np+1][2], s[2*np+1][3],
                         qh0, qh1, qh2, qh3, kl[np][1], kl[np][3]);
            }
#pragma unroll
            for (int np = 0; np < 4; np++) {
                mma_bf16(s[2*np][0], s[2*np][1], s[2*np][2], s[2*np][3],
                         ql0, ql1, ql2, ql3, kh[np][0], kh[np][2]);
                mma_bf16(s[2*np+1][0], s[2*np+1][1], s[2*np+1][2], s[2*np+1][3],
                         ql0, ql1, ql2, ql3, kh[np][1], kh[np][3]);
            }
        }

        const bool dm = (kt * 64 + 63) > rmin;
#pragma unroll
        for (int nt = 0; nt < 8; nt++) {
            int colb = kt * 64 + nt * 8 + 2 * t;
#pragma unroll
            for (int e = 0; e < 4; e++) {
                float v = s[nt][e] * scale;
                if (dm && (colb + (e & 1)) > (rmin + g + (e >> 1) * 8)) v = -1e30f;
                s[nt][e] = v;
            }
        }

        float rm0 = -1e30f, rm1 = -1e30f;
#pragma unroll
        for (int nt = 0; nt < 8; nt++) {
            rm0 = fmaxf(rm0, fmaxf(s[nt][0], s[nt][1]));
            rm1 = fmaxf(rm1, fmaxf(s[nt][2], s[nt][3]));
        }
        rm0 = fmaxf(rm0, __shfl_xor_sync(0xffffffffu, rm0, 1));
        rm0 = fmaxf(rm0, __shfl_xor_sync(0xffffffffu, rm0, 2));
        rm1 = fmaxf(rm1, __shfl_xor_sync(0xffffffffu, rm1, 1));
        rm1 = fmaxf(rm1, __shfl_xor_sync(0xffffffffu, rm1, 2));
        float mn0 = fmaxf(m0, rm0), mn1 = fmaxf(m1, rm1);
        float a0 = __expf(m0 - mn0), a1 = __expf(m1 - mn1);
        m0 = mn0; m1 = mn1;
        float ls0 = 0.f, ls1 = 0.f;
#pragma unroll
        for (int nt = 0; nt < 8; nt++) {
            s[nt][0] = __expf(s[nt][0] - mn0);
            s[nt][1] = __expf(s[nt][1] - mn0);
            s[nt][2] = __expf(s[nt][2] - mn1);
            s[nt][3] = __expf(s[nt][3] - mn1);
            ls0 += s[nt][0] + s[nt][1];
            ls1 += s[nt][2] + s[nt][3];
        }
        ls0 += __shfl_xor_sync(0xffffffffu, ls0, 1);
        ls0 += __shfl_xor_sync(0xffffffffu, ls0, 2);
        ls1 += __shfl_xor_sync(0xffffffffu, ls1, 1);
        ls1 += __shfl_xor_sync(0xffffffffu, ls1, 2);
        l0 = l0 * a0 + ls0;
        l1 = l1 * a1 + ls1;
#pragma unroll
        for (int nt = 0; nt < 16; nt++) {
            o[nt][0] *= a0; o[nt][1] *= a0;
            o[nt][2] *= a1; o[nt][3] *= a1;
        }

        uint32_t pah[4][4], pal[4][4];
#pragma unroll
        for (int k2 = 0; k2 < 4; k2++) {
            split2(s[2 * k2][0],     s[2 * k2][1],     pah[k2][0], pal[k2][0]);
            split2(s[2 * k2][2],     s[2 * k2][3],     pah[k2][1], pal[k2][1]);
            split2(s[2 * k2 + 1][0], s[2 * k2 + 1][1], pah[k2][2], pal[k2][2]);
            split2(s[2 * k2 + 1][2], s[2 * k2 + 1][3], pah[k2][3], pal[k2][3]);
        }

        // PV, term-major over np-halves (RAW distance 8)
#pragma unroll
        for (int k2 = 0; k2 < 4; k2++) {
#pragma unroll
            for (int half = 0; half < 2; half++) {
                uint32_t vh[4][4], vl[4][4];
#pragma unroll
                for (int j = 0; j < 4; j++) {
                    int np = half * 4 + j;
                    uint32_t va = sb2 + 2 * (VHO + k2 * 16 * FS + LM + np * 16);
                    ldsm4t(vh[j][0], vh[j][1], vh[j][2], vh[j][3], va);
                    ldsm4t(vl[j][0], vl[j][1], vl[j][2], vl[j][3], va + 2 * (VLO - VHO));
                }
#pragma unroll
                for (int j = 0; j < 4; j++) {
                    int np = half * 4 + j;
                    mma_bf16(o[2*np][0], o[2*np][1], o[2*np][2], o[2*np][3],
                             pah[k2][0], pah[k2][1], pah[k2][2], pah[k2][3],
                             vh[j][0], vh[j][1]);
                    mma_bf16(o[2*np+1][0], o[2*np+1][1], o[2*np+1][2], o[2*np+1][3],
                             pah[k2][0], pah[k2][1], pah[k2][2], pah[k2][3],
                             vh[j][2], vh[j][3]);
                }
#pragma unroll
                for (int j = 0; j < 4; j++) {
                    int np = half * 4 + j;
                    mma_bf16(o[2*np][0], o[2*np][1], o[2*np][2], o[2*np][3],
                             pal[k2][0], pal[k2][1], pal[k2][2], pal[k2][3],
                             vh[j][0], vh[j][1]);
                    mma_bf16(o[2*np+1][0], o[2*np+1][1], o[2*np+1][2], o[2*np+1][3],
                             pal[k2][0], pal[k2][1], pal[k2][2], pal[k2][3],
                             vh[j][2], vh[j][3]);
                }
#pragma unroll
                for (int j = 0; j < 4; j++) {
                    int np = half * 4 + j;
                    mma_bf16(o[2*np][0], o[2*np][1], o[2*np][2], o[2*np][3],
                             pah[k2][0], pah[k2][1], pah[k2][2], pah[k2][3],
                             vl[j][0], vl[j][1]);
                    mma_bf16(o[2*np+1][0], o[2*np+1][1], o[2*np+1][2], o[2*np+1][3],
                             pah[k2][0], pah[k2][1], pah[k2][2], pah[k2][3],
                             vl[j][2], vl[j][3]);
                }
            }
        }
    }

    // epilogue: normalize and write split bf16 hi/lo directly
    float i0 = 1.f / l0, i1 = 1.f / l1;
    __nv_bfloat16* oh0 = g_ah + (size_t)(rmin + g) * DIM + h * HD;
    __nv_bfloat16* ol0 = g_al + (size_t)(rmin + g) * DIM + h * HD;
    __nv_bfloat16* oh1 = g_ah + (size_t)(rmin + g + 8) * DIM + h * HD;
    __nv_bfloat16* ol1 = g_al + (size_t)(rmin + g + 8) * DIM + h * HD;
#pragma unroll
    for (int nt = 0; nt < 16; nt++) {
        int col = nt * 8 + 2 * t;
        uint32_t hh, ll;
        split2(o[nt][0] * i0, o[nt][1] * i0, hh, ll);
        *(uint32_t*)(oh0 + col) = hh;
        *(uint32_t*)(ol0 + col) = ll;
        split2(o[nt][2] * i1, o[nt][3] * i1, hh, ll);
        *(uint32_t*)(oh1 + col) = hh;
        *(uint32_t*)(ol1 + col) = ll;
    }
}

// ---------------------------------------------------------------------------
extern "C" void kernel_launch(void* const* d_in, const int* in_sizes, int n_in,
                              void* d_out, int out_size)
{
    const float* x  = (const float*)d_in[0];
    const float* wq = (const float*)d_in[1];
    const float* wk = (const float*)d_in[2];
    const float* wv = (const float*)d_in[3];
    const float* wo = (const float*)d_in[4];
    const float* fc = (const float*)d_in[7];
    const float* fs = (const float*)d_in[8];
    float* out = (float*)d_out;
    (void)in_sizes; (void)n_in; (void)out_size;

    static float* qkv = nullptr;
    static __nv_bfloat16 *xh, *xl, *wAh, *wAl, *woh, *wol, *ah, *al;
    if (!qkv) {   // first call is the uncaptured correctness run
        cudaGetSymbolAddress((void**)&qkv, g_qkv);
        cudaGetSymbolAddress((void**)&xh, g_xh);   cudaGetSymbolAddress((void**)&xl, g_xl);
        cudaGetSymbolAddress((void**)&wAh, g_wAh); cudaGetSymbolAddress((void**)&wAl, g_wAl);
        cudaGetSymbolAddress((void**)&woh, g_woh); cudaGetSymbolAddress((void**)&wol, g_wol);
        cudaGetSymbolAddress((void**)&ah, g_ah);   cudaGetSymbolAddress((void**)&al, g_al);
        cudaFuncSetAttribute(gemm_mma2,
                             cudaFuncAttributeMaxDynamicSharedMemorySize, GEMM_SMEM);
        cudaFuncSetAttribute(flash_mma,
                             cudaFuncAttributeMaxDynamicSharedMemorySize, FLASH_SMEM2);
    }

    // fp32 -> bf16 hi/lo splits (wq|wk|wv fused into one [6144 x 4096] buffer)
    split_kernel<<<(SEQ * DIM / 4 + 255) / 256, 256>>>(x, xh, xl, SEQ * DIM / 4);
    split_kernel<<<(DIM * DIM / 4 + 255) / 256, 256>>>(wq, wAh, wAl, DIM * DIM / 4);
    split_kernel<<<(KVD * DIM / 4 + 255) / 256, 256>>>(
        wk, wAh + (size_t)DIM * DIM, wAl + (size_t)DIM * DIM, KVD * DIM / 4);
    split_kernel<<<(KVD * DIM / 4 + 255) / 256, 256>>>(
        wv, wAh + (size_t)(DIM + KVD) * DIM, wAl + (size_t)(DIM + KVD) * DIM, KVD * DIM / 4);
    split_kernel<<<(DIM * DIM / 4 + 255) / 256, 256>>>(wo, woh, wol, DIM * DIM / 4);

    // Fused QKV projection (one GEMM, N = 6144) -> g_qkv [S, 6144]
    gemm_mma2<<<dim3(QKV_W / 256, SEQ / 128), 256, GEMM_SMEM>>>(
        xh, xl, wAh, wAl, qkv, QKV_W, DIM);

    // RoPE on Q + K in place
    rope_kernel<<<SEQ * 40 * 64 / 256, 256>>>(fc, fs);

    // Causal GQA flash attention -> g_ah/g_al (bf16 split, no fp32 round trip)
    flash_mma<<<dim3(SEQ / 128, NH), 256, FLASH_SMEM2>>>();

    // Output projection
    gemm_mma2<<<dim3(DIM / 256, SEQ / 128), 256, GEMM_SMEM>>>(
        ah, al, woh, wol, out, DIM, DIM);
}

// round 9
// speedup vs baseline: 1.5179x; 1.5179x over previous
#include <cuda_runtime.h>
#include <cuda_bf16.h>
#include <math.h>
#include <cstdint>

#define SEQ   2048
#define DIM   4096
#define NH    32
#define NKV   8
#define HD    128
#define KVD   (NKV * HD)             /* 1024 */
#define QKV_W (DIM + 2 * KVD)        /* 6144: [q 4096 | k 1024 | v 1024] per row */

// ---------------------------------------------------------------------------
// Scratch (__device__ globals — the sanctioned allocation mechanism)
// ---------------------------------------------------------------------------
__device__ float g_qkv[SEQ * QKV_W];
__device__ __nv_bfloat16 g_xh[SEQ * DIM],    g_xl[SEQ * DIM];
__device__ __nv_bfloat16 g_wAh[QKV_W * DIM], g_wAl[QKV_W * DIM];  // wq|wk|wv fused
__device__ __nv_bfloat16 g_woh[DIM * DIM],   g_wol[DIM * DIM];
__device__ __nv_bfloat16 g_ah[SEQ * DIM],    g_al[SEQ * DIM];     // flash output (split)

// ---------------------------------------------------------------------------
// helpers
// ---------------------------------------------------------------------------
__device__ __forceinline__ uint32_t smem_u32(const void* p) {
    uint32_t a;
    asm("{ .reg .u64 t; cvta.to.shared.u64 t, %1; cvt.u32.u64 %0, t; }"
        : "=r"(a) : "l"(p));
    return a;
}
__device__ __forceinline__ void cp_async16(uint32_t dst, const void* src) {
    asm volatile("cp.async.cg.shared.global [%0], [%1], 16;"
                 :: "r"(dst), "l"(src));
}
__device__ __forceinline__ void mma_bf16(float& d0, float& d1, float& d2, float& d3,
                                         uint32_t a0, uint32_t a1, uint32_t a2, uint32_t a3,
                                         uint32_t b0, uint32_t b1)
{
    asm volatile(
        "mma.sync.aligned.m16n8k16.row.col.f32.bf16.bf16.f32 "
        "{%0,%1,%2,%3}, {%4,%5,%6,%7}, {%8,%9}, {%0,%1,%2,%3};"
        : "+f"(d0), "+f"(d1), "+f"(d2), "+f"(d3)
        : "r"(a0), "r"(a1), "r"(a2), "r"(a3), "r"(b0), "r"(b1));
}
__device__ __forceinline__ void ldsm4(uint32_t& r0, uint32_t& r1, uint32_t& r2,
                                      uint32_t& r3, uint32_t a)
{
    asm volatile("ldmatrix.sync.aligned.m8n8.x4.shared.b16 {%0,%1,%2,%3}, [%4];"
                 : "=r"(r0), "=r"(r1), "=r"(r2), "=r"(r3) : "r"(a));
}
__device__ __forceinline__ void ldsm4t(uint32_t& r0, uint32_t& r1, uint32_t& r2,
                                       uint32_t& r3, uint32_t a)
{
    asm volatile("ldmatrix.sync.aligned.m8n8.x4.trans.shared.b16 {%0,%1,%2,%3}, [%4];"
                 : "=r"(r0), "=r"(r1), "=r"(r2), "=r"(r3) : "r"(a));
}
__device__ __forceinline__ void split4(float4 v, uint2& h, uint2& l) {
    __nv_bfloat16 h0 = __float2bfloat16(v.x), h1 = __float2bfloat16(v.y);
    __nv_bfloat16 h2 = __float2bfloat16(v.z), h3 = __float2bfloat16(v.w);
    __nv_bfloat162 ha(h0, h1), hb(h2, h3);
    __nv_bfloat162 la(__float2bfloat16(v.x - __bfloat162float(h0)),
                      __float2bfloat16(v.y - __bfloat162float(h1)));
    __nv_bfloat162 lb(__float2bfloat16(v.z - __bfloat162float(h2)),
                      __float2bfloat16(v.w - __bfloat162float(h3)));
    h = make_uint2(*(uint32_t*)&ha, *(uint32_t*)&hb);
    l = make_uint2(*(uint32_t*)&la, *(uint32_t*)&lb);
}
__device__ __forceinline__ void split2(float x, float y, uint32_t& h, uint32_t& l) {
    __nv_bfloat16 hx = __float2bfloat16(x), hy = __float2bfloat16(y);
    __nv_bfloat162 hv(hx, hy);
    __nv_bfloat162 lv(__float2bfloat16(x - __bfloat162float(hx)),
                      __float2bfloat16(y - __bfloat162float(hy)));
    h = *(uint32_t*)&hv;
    l = *(uint32_t*)&lv;
}

// ---------------------------------------------------------------------------
// fp32 -> bf16 hi/lo split (vectorized x4)
// ---------------------------------------------------------------------------
__global__ void split_kernel(const float* __restrict__ src,
                             __nv_bfloat16* __restrict__ hi,
                             __nv_bfloat16* __restrict__ lo, int n4)
{
    int i = blockIdx.x * blockDim.x + threadIdx.x;
    if (i >= n4) return;
    float4 v = ((const float4*)src)[i];
    uint2 h, l;
    split4(v, h, l);
    ((uint2*)hi)[i] = h;
    ((uint2*)lo)[i] = l;
}

// ---------------------------------------------------------------------------
// HMMA GEMM: C[M,N] = A[M,K] * B[N,K]^T, bf16x3 split, fp32 accum.
// 128x256 block tile, warp tile 64x64 (8 warps 2x4), BK=32.
// R7 structure (b-frags loaded per-ng); within each ng the MMA order is
// term-outer / mt-inner so each accumulator's split terms are 8 MMAs apart.
// ---------------------------------------------------------------------------
#define AH3   0
#define AL3   (128 * 32)
#define BH3   (2 * 128 * 32)
#define BL3   (BH3 + 256 * 32)
#define STG3  (BH3 + 2 * 256 * 32)       /* 24576 halfs = 49152 B */
#define GEMM_SMEM (4 * STG3 * 2)         /* 196608 B */

__global__ void __launch_bounds__(256, 1) gemm_mma2(
    const __nv_bfloat16* __restrict__ Ah, const __nv_bfloat16* __restrict__ Al,
    const __nv_bfloat16* __restrict__ Bh, const __nv_bfloat16* __restrict__ Bl,
    float* __restrict__ C, int ldc, int K)
{
    extern __shared__ __nv_bfloat16 sm3[];
    const uint32_t sbase = smem_u32(sm3);
    const int tid = threadIdx.x;
    const int wid = tid >> 5, lane = tid & 31;
    const int warp_m = wid & 1, warp_n = wid >> 1;      // 2 x 4 warp grid
    const int g = lane >> 2, t = lane & 3;
    const int m0 = blockIdx.y * 128, n0 = blockIdx.x * 256;

    const int rl = lane & 15;
    const int sw = (rl >> 1) & 3;
    const int ch = lane >> 4;
    const uint32_t LM0 = rl * 32 + (((ch + 0) ^ sw) << 3);
    const uint32_t LM1 = rl * 32 + (((ch + 2) ^ sw) << 3);

    const __nv_bfloat16* gAh = Ah + (size_t)m0 * K;
    const __nv_bfloat16* gAl = Al + (size_t)m0 * K;
    const __nv_bfloat16* gBh = Bh + (size_t)n0 * K;
    const __nv_bfloat16* gBl = Bl + (size_t)n0 * K;

    float d[4][8][4];
#pragma unroll
    for (int i = 0; i < 4; i++)
#pragma unroll
        for (int j = 0; j < 8; j++)
#pragma unroll
            for (int e = 0; e < 4; e++) d[i][j][e] = 0.f;

    const int nk = K / 32;

    auto issue = [&](int s, int buf) {
        const int koff = s * 32;
        const uint32_t stg = sbase + (uint32_t)buf * (STG3 * 2);
#pragma unroll
        for (int j = 0; j < 12; j++) {
            int idx = tid + j * 256;
            const __nv_bfloat16* src;
            uint32_t off;
            int r;
            if (idx < 512)       { r = idx >> 2;          src = gAh; off = AH3; }
            else if (idx < 1024) { r = (idx - 512) >> 2;  src = gAl; off = AL3; }
            else if (idx < 2048) { r = (idx - 1024) >> 2; src = gBh; off = BH3; }
            else                 { r = (idx - 2048) >> 2; src = gBl; off = BL3; }
            int c = idx & 3;
            int cs = c ^ ((r >> 1) & 3);
            cp_async16(stg + 2 * (off + r * 32 + cs * 8),
                       src + (size_t)r * K + koff + c * 8);
        }
        asm volatile("cp.async.commit_group;" ::: "memory");
    };

    issue(0, 0);
    if (nk > 1) issue(1, 1);
    if (nk > 2) issue(2, 2);

    for (int s = 0; s < nk; s++) {
        const int buf = s & 3;
        if (s + 2 < nk)      asm volatile("cp.async.wait_group 2;" ::: "memory");
        else if (s + 1 < nk) asm volatile("cp.async.wait_group 1;" ::: "memory");
        else                 asm volatile("cp.async.wait_group 0;" ::: "memory");
        __syncthreads();
        if (s + 3 < nk) issue(s + 3, (s + 3) & 3);

        const uint32_t stg = sbase + (uint32_t)buf * (STG3 * 2);

#pragma unroll
        for (int ks = 0; ks < 2; ks++) {
            const uint32_t LM = ks ? LM1 : LM0;
            uint32_t aH[4][4], aL[4][4];
#pragma unroll
            for (int mt = 0; mt < 4; mt++) {
                uint32_t ab = stg + 2 * ((warp_m * 64 + mt * 16) * 32 + LM);
                ldsm4(aH[mt][0], aH[mt][1], aH[mt][2], aH[mt][3], ab + 2 * AH3);
                ldsm4(aL[mt][0], aL[mt][1], aL[mt][2], aL[mt][3], ab + 2 * AL3);
            }
#pragma unroll
            for (int ng = 0; ng < 4; ng++) {
                uint32_t bb = stg + 2 * ((warp_n * 64 + ng * 16) * 32 + LM);
                uint32_t bh0, bh1, bh2, bh3, bl0, bl1, bl2, bl3;
                ldsm4(bh0, bh1, bh2, bh3, bb + 2 * BH3);
                ldsm4(bl0, bl1, bl2, bl3, bb + 2 * BL3);
                // term 1 (Ah*Bh): 8 MMAs, all-distinct accumulators
#pragma unroll
                for (int mt = 0; mt < 4; mt++) {
                    float* de = d[mt][2 * ng];
                    float* dc = d[mt][2 * ng + 1];
                    mma_bf16(de[0], de[1], de[2], de[3],
                             aH[mt][0], aH[mt][1], aH[mt][2], aH[mt][3], bh0, bh2);
                    mma_bf16(dc[0], dc[1], dc[2], dc[3],
                             aH[mt][0], aH[mt][1], aH[mt][2], aH[mt][3], bh1, bh3);
                }
                // term 2 (Ah*Bl)
#pragma unroll
                for (int mt = 0; mt < 4; mt++) {
                    float* de = d[mt][2 * ng];
                    float* dc = d[mt][2 * ng + 1];
                    mma_bf16(de[0], de[1], de[2], de[3],
                             aH[mt][0], aH[mt][1], aH[mt][2], aH[mt][3], bl0, bl2);
                    mma_bf16(dc[0], dc[1], dc[2], dc[3],
                             aH[mt][0], aH[mt][1], aH[mt][2], aH[mt][3], bl1, bl3);
                }
                // term 3 (Al*Bh)
#pragma unroll
                for (int mt = 0; mt < 4; mt++) {
                    float* de = d[mt][2 * ng];
                    float* dc = d[mt][2 * ng + 1];
                    mma_bf16(de[0], de[1], de[2], de[3],
                             aL[mt][0], aL[mt][1], aL[mt][2], aL[mt][3], bh0, bh2);
                    mma_bf16(dc[0], dc[1], dc[2], dc[3],
                             aL[mt][0], aL[mt][1], aL[mt][2], aL[mt][3], bh1, bh3);
                }
            }
        }
        __syncthreads();
    }

    // epilogue
#pragma unroll
    for (int mt = 0; mt < 4; mt++) {
        const int row = m0 + warp_m * 64 + mt * 16 + g;
#pragma unroll
        for (int nt = 0; nt < 8; nt++) {
            const int col = n0 + warp_n * 64 + nt * 8 + 2 * t;
            *(float2*)(C + (size_t)row * ldc + col) =
                make_float2(d[mt][nt][0], d[mt][nt][1]);
            *(float2*)(C + (size_t)(row + 8) * ldc + col) =
                make_float2(d[mt][nt][2], d[mt][nt][3]);
        }
    }
}

// ---------------------------------------------------------------------------
// RoPE in-place on Q (heads 0..31) and K (heads 32..39) inside g_qkv.
// ---------------------------------------------------------------------------
__global__ void rope_kernel(const float* __restrict__ cosb,
                            const float* __restrict__ sinb)
{
    int idx = blockIdx.x * blockDim.x + threadIdx.x;
    int p = idx & 63;
    int h = (idx >> 6) % 40;
    int s = idx / (64 * 40);
    float c  = cosb[s * 64 + p];
    float sn = sinb[s * 64 + p];
    float* base = g_qkv + (size_t)s * QKV_W
                + (h < NH ? h * HD : DIM + (h - NH) * HD) + 2 * p;
    float re = base[0], im = base[1];
    base[0] = re * c - im * sn;
    base[1] = re * sn + im * c;
}

// ---------------------------------------------------------------------------
// Tensor-core flash attention.  Block = 128 q x 1 head, 8 warps x 16 rows.
// R6/R7 structure; within each np the se/so (oe/oo) MMAs are interleaved
// across terms (RAW distance 2 instead of 1).  Epilogue writes bf16 hi/lo.
// ---------------------------------------------------------------------------
#define FS    136
#define QHO   0
#define QLO   17408
#define KHO   34816
#define KLO   43520
#define VHO   52224
#define VLO   60928
#define FLASH_SMEM2 (69632 * 2)

__global__ void __launch_bounds__(256, 1) flash_mma()
{
    extern __shared__ __nv_bfloat16 sb[];
    const uint32_t sb2 = smem_u32(sb);
    const int qt = blockIdx.x, h = blockIdx.y;
    const int q0 = qt * 128;
    const int kvh = h >> 2;
    const int tid = threadIdx.x;
    const int wid = tid >> 5, lane = tid & 31;
    const int g = lane >> 2, t = lane & 3;
    const int rmin = q0 + wid * 16;
    const uint32_t LM = (lane & 15) * FS + ((lane >> 4) << 3);

    const float* qb = g_qkv + (size_t)q0 * QKV_W + h * HD;
#pragma unroll
    for (int p = 0; p < 16; p++) {
        int i = tid + p * 256;
        int r = i >> 5, c4 = i & 31;
        float4 v = *(const float4*)(qb + (size_t)r * QKV_W + c4 * 4);
        uint2 hh, ll;
        split4(v, hh, ll);
        int o = r * FS + c4 * 4;
        *(uint2*)&sb[QHO + o] = hh;
        *(uint2*)&sb[QLO + o] = ll;
    }

    float m0 = -1e30f, m1 = -1e30f, l0 = 0.f, l1 = 0.f;
    float o[16][4];
#pragma unroll
    for (int i = 0; i < 16; i++)
#pragma unroll
        for (int e = 0; e < 4; e++) o[i][e] = 0.f;

    const float scale = 0.08838834764831845f;
    const int nkt = 2 * (qt + 1);

    for (int kt = 0; kt < nkt; kt++) {
        __syncthreads();
        const float* kb = g_qkv + (size_t)(kt * 64) * QKV_W + DIM + kvh * HD;
        const float* vb = kb + KVD;
#pragma unroll
        for (int p = 0; p < 8; p++) {
            int i = tid + p * 256;
            int r = i >> 5, c4 = i & 31;
            int o2 = r * FS + c4 * 4;
            float4 kv = *(const float4*)(kb + (size_t)r * QKV_W + c4 * 4);
            uint2 hh, ll;
            split4(kv, hh, ll);
            *(uint2*)&sb[KHO + o2] = hh;
            *(uint2*)&sb[KLO + o2] = ll;
            float4 vv = *(const float4*)(vb + (size_t)r * QKV_W + c4 * 4);
            split4(vv, hh, ll);
            *(uint2*)&sb[VHO + o2] = hh;
            *(uint2*)&sb[VLO + o2] = ll;
        }
        __syncthreads();

        if (kt * 64 > rmin + 15) continue;

        float s[8][4];
#pragma unroll
        for (int i = 0; i < 8; i++)
#pragma unroll
            for (int e = 0; e < 4; e++) s[i][e] = 0.f;

#pragma unroll
        for (int ks = 0; ks < 8; ks++) {
            uint32_t qa = sb2 + 2 * (QHO + wid * 16 * FS + LM + ks * 16);
            uint32_t qh0, qh1, qh2, qh3, ql0, ql1, ql2, ql3;
            ldsm4(qh0, qh1, qh2, qh3, qa);
            ldsm4(ql0, ql1, ql2, ql3, qa + 2 * (QLO - QHO));
#pragma unroll
            for (int np = 0; np < 4; np++) {
                uint32_t ka = sb2 + 2 * (KHO + np * 16 * FS + LM + ks * 16);
                uint32_t kh0, kh1, kh2, kh3, kl0, kl1, kl2, kl3;
                ldsm4(kh0, kh1, kh2, kh3, ka);
                ldsm4(kl0, kl1, kl2, kl3, ka + 2 * (KLO - KHO));
                float* se = s[2 * np];
                float* so = s[2 * np + 1];
                // interleave across accumulators: RAW distance 2
                mma_bf16(se[0], se[1], se[2], se[3], qh0, qh1, qh2, qh3, kh0, kh2);
                mma_bf16(so[0], so[1], so[2], so[3], qh0, qh1, qh2, qh3, kh1, kh3);
                mma_bf16(se[0], se[1], se[2], se[3], qh0, qh1, qh2, qh3, kl0, kl2);
                mma_bf16(so[0], so[1], so[2], so[3], qh0, qh1, qh2, qh3, kl1, kl3);
                mma_bf16(se[0], se[1], se[2], se[3], ql0, ql1, ql2, ql3, kh0, kh2);
                mma_bf16(so[0], so[1], so[2], so[3], ql0, ql1, ql2, ql3, kh1, kh3);
            }
        }

        const bool dm = (kt * 64 + 63) > rmin;
#pragma unroll
        for (int nt = 0; nt < 8; nt++) {
            int colb = kt * 64 + nt * 8 + 2 * t;
#pragma unroll
            for (int e = 0; e < 4; e++) {
                float v = s[nt][e] * scale;
                if (dm && (colb + (e & 1)) > (rmin + g + (e >> 1) * 8)) v = -1e30f;
                s[nt][e] = v;
            }
        }

        float rm0 = -1e30f, rm1 = -1e30f;
#pragma unroll
        for (int nt = 0; nt < 8; nt++) {
            rm0 = fmaxf(rm0, fmaxf(s[nt][0], s[nt][1]));
            rm1 = fmaxf(rm1, fmaxf(s[nt][2], s[nt][3]));
        }
        rm0 = fmaxf(rm0, __shfl_xor_sync(0xffffffffu, rm0, 1));
        rm0 = fmaxf(rm0, __shfl_xor_sync(0xffffffffu, rm0, 2));
        rm1 = fmaxf(rm1, __shfl_xor_sync(0xffffffffu, rm1, 1));
        rm1 = fmaxf(rm1, __shfl_xor_sync(0xffffffffu, rm1, 2));
        float mn0 = fmaxf(m0, rm0), mn1 = fmaxf(m1, rm1);
        float a0 = __expf(m0 - mn0), a1 = __expf(m1 - mn1);
        m0 = mn0; m1 = mn1;
        float ls0 = 0.f, ls1 = 0.f;
#pragma unroll
        for (int nt = 0; nt < 8; nt++) {
            s[nt][0] = __expf(s[nt][0] - mn0);
            s[nt][1] = __expf(s[nt][1] - mn0);
            s[nt][2] = __expf(s[nt][2] - mn1);
            s[nt][3] = __expf(s[nt][3] - mn1);
            ls0 += s[nt][0] + s[nt][1];
            ls1 += s[nt][2] + s[nt][3];
        }
        ls0 += __shfl_xor_sync(0xffffffffu, ls0, 1);
        ls0 += __shfl_xor_sync(0xffffffffu, ls0, 2);
        ls1 += __shfl_xor_sync(0xffffffffu, ls1, 1);
        ls1 += __shfl_xor_sync(0xffffffffu, ls1, 2);
        l0 = l0 * a0 + ls0;
        l1 = l1 * a1 + ls1;
#pragma unroll
        for (int nt = 0; nt < 16; nt++) {
            o[nt][0] *= a0; o[nt][1] *= a0;
            o[nt][2] *= a1; o[nt][3] *= a1;
        }

        uint32_t pah[4][4], pal[4][4];
#pragma unroll
        for (int k2 = 0; k2 < 4; k2++) {
            split2(s[2 * k2][0],     s[2 * k2][1],     pah[k2][0], pal[k2][0]);
            split2(s[2 * k2][2],     s[2 * k2][3],     pah[k2][1], pal[k2][1]);
            split2(s[2 * k2 + 1][0], s[2 * k2 + 1][1], pah[k2][2], pal[k2][2]);
            split2(s[2 * k2 + 1][2], s[2 * k2 + 1][3], pah[k2][3], pal[k2][3]);
        }

#pragma unroll
        for (int k2 = 0; k2 < 4; k2++) {
#pragma unroll
            for (int np = 0; np < 8; np++) {
                uint32_t va = sb2 + 2 * (VHO + k2 * 16 * FS + LM + np * 16);
                uint32_t vh0, vh1, vh2, vh3, vl0, vl1, vl2, vl3;
                ldsm4t(vh0, vh1, vh2, vh3, va);
                ldsm4t(vl0, vl1, vl2, vl3, va + 2 * (VLO - VHO));
                float* oe = o[2 * np];
                float* oo = o[2 * np + 1];
                // interleave across accumulators: RAW distance 2
                mma_bf16(oe[0], oe[1], oe[2], oe[3],
                         pah[k2][0], pah[k2][1], pah[k2][2], pah[k2][3], vh0, vh1);
                mma_bf16(oo[0], oo[1], oo[2], oo[3],
                         pah[k2][0], pah[k2][1], pah[k2][2], pah[k2][3], vh2, vh3);
                mma_bf16(oe[0], oe[1], oe[2], oe[3],
                         pal[k2][0], pal[k2][1], pal[k2][2], pal[k2][3], vh0, vh1);
                mma_bf16(oo[0], oo[1], oo[2], oo[3],
                         pal[k2][0], pal[k2][1], pal[k2][2], pal[k2][3], vh2, vh3);
                mma_bf16(oe[0], oe[1], oe[2], oe[3],
                         pah[k2][0], pah[k2][1], pah[k2][2], pah[k2][3], vl0, vl1);
                mma_bf16(oo[0], oo[1], oo[2], oo[3],
                         pah[k2][0], pah[k2][1], pah[k2][2], pah[k2][3], vl2, vl3);
            }
        }
    }

    // epilogue: normalize and write bf16 hi/lo splits directly
    float i0 = 1.f / l0, i1 = 1.f / l1;
    __nv_bfloat16* oh0 = g_ah + (size_t)(rmin + g) * DIM + h * HD;
    __nv_bfloat16* ol0 = g_al + (size_t)(rmin + g) * DIM + h * HD;
    __nv_bfloat16* oh1 = g_ah + (size_t)(rmin + g + 8) * DIM + h * HD;
    __nv_bfloat16* ol1 = g_al + (size_t)(rmin + g + 8) * DIM + h * HD;
#pragma unroll
    for (int nt = 0; nt < 16; nt++) {
        int col = nt * 8 + 2 * t;
        uint32_t hh, ll;
        split2(o[nt][0] * i0, o[nt][1] * i0, hh, ll);
        *(uint32_t*)(oh0 + col) = hh;
        *(uint32_t*)(ol0 + col) = ll;
        split2(o[nt][2] * i1, o[nt][3] * i1, hh, ll);
        *(uint32_t*)(oh1 + col) = hh;
        *(uint32_t*)(ol1 + col) = ll;
    }
}

// ---------------------------------------------------------------------------
extern "C" void kernel_launch(void* const* d_in, const int* in_sizes, int n_in,
                              void* d_out, int out_size)
{
    const float* x  = (const float*)d_in[0];
    const float* wq = (const float*)d_in[1];
    const float* wk = (const float*)d_in[2];
    const float* wv = (const float*)d_in[3];
    const float* wo = (const float*)d_in[4];
    const float* fc = (const float*)d_in[7];
    const float* fs = (const float*)d_in[8];
    float* out = (float*)d_out;
    (void)in_sizes; (void)n_in; (void)out_size;

    static float* qkv = nullptr;
    static __nv_bfloat16 *xh, *xl, *wAh, *wAl, *woh, *wol, *ah, *al;
    if (!qkv) {   // first call is the uncaptured correctness run
        cudaGetSymbolAddress((void**)&qkv, g_qkv);
        cudaGetSymbolAddress((void**)&xh, g_xh);   cudaGetSymbolAddress((void**)&xl, g_xl);
        cudaGetSymbolAddress((void**)&wAh, g_wAh); cudaGetSymbolAddress((void**)&wAl, g_wAl);
        cudaGetSymbolAddress((void**)&woh, g_woh); cudaGetSymbolAddress((void**)&wol, g_wol);
        cudaGetSymbolAddress((void**)&ah, g_ah);   cudaGetSymbolAddress((void**)&al, g_al);
        cudaFuncSetAttribute(gemm_mma2,
                             cudaFuncAttributeMaxDynamicSharedMemorySize, GEMM_SMEM);
        cudaFuncSetAttribute(flash_mma,
                             cudaFuncAttributeMaxDynamicSharedMemorySize, FLASH_SMEM2);
    }

    // fp32 -> bf16 hi/lo splits (wq|wk|wv fused into one [6144 x 4096] buffer)
    split_kernel<<<(SEQ * DIM / 4 + 255) / 256, 256>>>(x, xh, xl, SEQ * DIM / 4);
    split_kernel<<<(DIM * DIM / 4 + 255) / 256, 256>>>(wq, wAh, wAl, DIM * DIM / 4);
    split_kernel<<<(KVD * DIM / 4 + 255) / 256, 256>>>(
        wk, wAh + (size_t)DIM * DIM, wAl + (size_t)DIM * DIM, KVD * DIM / 4);
    split_kernel<<<(KVD * DIM / 4 + 255) / 256, 256>>>(
        wv, wAh + (size_t)(DIM + KVD) * DIM, wAl + (size_t)(DIM + KVD) * DIM, KVD * DIM / 4);
    split_kernel<<<(DIM * DIM / 4 + 255) / 256, 256>>>(wo, woh, wol, DIM * DIM / 4);

    // Fused QKV projection (one GEMM, N = 6144) -> g_qkv [S, 6144]
    gemm_mma2<<<dim3(QKV_W / 256, SEQ / 128), 256, GEMM_SMEM>>>(
        xh, xl, wAh, wAl, qkv, QKV_W, DIM);

    // RoPE on Q + K in place
    rope_kernel<<<SEQ * 40 * 64 / 256, 256>>>(fc, fs);

    // Causal GQA flash attention -> g_ah/g_al (bf16 split, no fp32 round trip)
    flash_mma<<<dim3(SEQ / 128, NH), 256, FLASH_SMEM2>>>();

    // Output projection
    gemm_mma2<<<dim3(DIM / 256, SEQ / 128), 256, GEMM_SMEM>>>(
        ah, al, woh, wol, out, DIM, DIM);
}

// round 10
// speedup vs baseline: 2.1860x; 1.4401x over previous
#include <cuda_runtime.h>
#include <cuda_fp16.h>
#include <math.h>
#include <cstdint>

#define SEQ   2048
#define DIM   4096
#define NH    32
#define NKV   8
#define HD    128
#define KVD   (NKV * HD)             /* 1024 */
#define QKV_W (DIM + 2 * KVD)        /* 6144: [q 4096 | k 1024 | v 1024] per row */

// ---------------------------------------------------------------------------
// Scratch (__device__ globals — the sanctioned allocation mechanism)
// ---------------------------------------------------------------------------
__device__ float g_qkv[SEQ * QKV_W];
__device__ __half g_xh[SEQ * DIM];
__device__ __half g_wAh[QKV_W * DIM], g_wAl[QKV_W * DIM];  // wq|wk|wv fused
__device__ __half g_woh[DIM * DIM],   g_wol[DIM * DIM];
__device__ __half g_ah[SEQ * DIM];                          // flash output (fp16)

// ---------------------------------------------------------------------------
// helpers
// ---------------------------------------------------------------------------
__device__ __forceinline__ uint32_t smem_u32(const void* p) {
    uint32_t a;
    asm("{ .reg .u64 t; cvta.to.shared.u64 t, %1; cvt.u32.u64 %0, t; }"
        : "=r"(a) : "l"(p));
    return a;
}
__device__ __forceinline__ void cp_async16(uint32_t dst, const void* src) {
    asm volatile("cp.async.cg.shared.global [%0], [%1], 16;"
                 :: "r"(dst), "l"(src));
}
__device__ __forceinline__ void mma_fp16(float& d0, float& d1, float& d2, float& d3,
                                         uint32_t a0, uint32_t a1, uint32_t a2, uint32_t a3,
                                         uint32_t b0, uint32_t b1)
{
    asm volatile(
        "mma.sync.aligned.m16n8k16.row.col.f32.f16.f16.f32 "
        "{%0,%1,%2,%3}, {%4,%5,%6,%7}, {%8,%9}, {%0,%1,%2,%3};"
        : "+f"(d0), "+f"(d1), "+f"(d2), "+f"(d3)
        : "r"(a0), "r"(a1), "r"(a2), "r"(a3), "r"(b0), "r"(b1));
}
__device__ __forceinline__ void ldsm4(uint32_t& r0, uint32_t& r1, uint32_t& r2,
                                      uint32_t& r3, uint32_t a)
{
    asm volatile("ldmatrix.sync.aligned.m8n8.x4.shared.b16 {%0,%1,%2,%3}, [%4];"
                 : "=r"(r0), "=r"(r1), "=r"(r2), "=r"(r3) : "r"(a));
}
__device__ __forceinline__ void ldsm4t(uint32_t& r0, uint32_t& r1, uint32_t& r2,
                                       uint32_t& r3, uint32_t a)
{
    asm volatile("ldmatrix.sync.aligned.m8n8.x4.trans.shared.b16 {%0,%1,%2,%3}, [%4];"
                 : "=r"(r0), "=r"(r1), "=r"(r2), "=r"(r3) : "r"(a));
}
__device__ __forceinline__ uint32_t pack2h(float x, float y) {
    __half2 hv = __halves2half2(__float2half_rn(x), __float2half_rn(y));
    return *(uint32_t*)&hv;
}
__device__ __forceinline__ void split4h(float4 v, uint2& h, uint2& l) {
    __half h0 = __float2half_rn(v.x), h1 = __float2half_rn(v.y);
    __half h2 = __float2half_rn(v.z), h3 = __float2half_rn(v.w);
    __half2 ha = __halves2half2(h0, h1), hb = __halves2half2(h2, h3);
    __half2 la = __halves2half2(__float2half_rn(v.x - __half2float(h0)),
                                __float2half_rn(v.y - __half2float(h1)));
    __half2 lb = __halves2half2(__float2half_rn(v.z - __half2float(h2)),
                                __float2half_rn(v.w - __half2float(h3)));
    h = make_uint2(*(uint32_t*)&ha, *(uint32_t*)&hb);
    l = make_uint2(*(uint32_t*)&la, *(uint32_t*)&lb);
}
__device__ __forceinline__ void conv4h(float4 v, uint2& h) {
    __half2 ha = __halves2half2(__float2half_rn(v.x), __float2half_rn(v.y));
    __half2 hb = __halves2half2(__float2half_rn(v.z), __float2half_rn(v.w));
    h = make_uint2(*(uint32_t*)&ha, *(uint32_t*)&hb);
}

// ---------------------------------------------------------------------------
// fp32 -> fp16 hi/lo split, and hi-only convert
// ---------------------------------------------------------------------------
__global__ void split_kernel(const float* __restrict__ src,
                             __half* __restrict__ hi,
                             __half* __restrict__ lo, int n4)
{
    int i = blockIdx.x * blockDim.x + threadIdx.x;
    if (i >= n4) return;
    float4 v = ((const float4*)src)[i];
    uint2 h, l;
    split4h(v, h, l);
    ((uint2*)hi)[i] = h;
    ((uint2*)lo)[i] = l;
}
__global__ void conv_kernel(const float* __restrict__ src,
                            __half* __restrict__ hi, int n4)
{
    int i = blockIdx.x * blockDim.x + threadIdx.x;
    if (i >= n4) return;
    float4 v = ((const float4*)src)[i];
    uint2 h;
    conv4h(v, h);
    ((uint2*)hi)[i] = h;
}

// ---------------------------------------------------------------------------
// HMMA GEMM (fp16 x2): C[M,N] = A[M,K]*B[N,K]^T ≈ Ah*Bh + Ah*Bl, fp32 accum.
// 128x256 block tile, warp 64x64 (2x4), BK=32, 4-stage cp.async, XOR swizzle.
// Stage = Ah(128) | Bh(256) | Bl(256) rows of 64 B.
// ---------------------------------------------------------------------------
#define AH3   0
#define BH3   (128 * 32)                 /* 4096  halfs */
#define BL3   (BH3 + 256 * 32)           /* 12288 halfs */
#define STG3  (BL3 + 256 * 32)           /* 20480 halfs = 40960 B */
#define GEMM_SMEM (4 * STG3 * 2)         /* 163840 B */

__global__ void __launch_bounds__(256, 1) gemm_mma2(
    const __half* __restrict__ Ah,
    const __half* __restrict__ Bh, const __half* __restrict__ Bl,
    float* __restrict__ C, int ldc, int K)
{
    extern __shared__ __half sm3[];
    const uint32_t sbase = smem_u32(sm3);
    const int tid = threadIdx.x;
    const int wid = tid >> 5, lane = tid & 31;
    const int warp_m = wid & 1, warp_n = wid >> 1;      // 2 x 4 warp grid
    const int g = lane >> 2, t = lane & 3;
    const int m0 = blockIdx.y * 128, n0 = blockIdx.x * 256;

    const int rl = lane & 15;
    const int sw = (rl >> 1) & 3;
    const int ch = lane >> 4;
    const uint32_t LM0 = rl * 32 + (((ch + 0) ^ sw) << 3);
    const uint32_t LM1 = rl * 32 + (((ch + 2) ^ sw) << 3);

    const __half* gAh = Ah + (size_t)m0 * K;
    const __half* gBh = Bh + (size_t)n0 * K;
    const __half* gBl = Bl + (size_t)n0 * K;

    float d[4][8][4];
#pragma unroll
    for (int i = 0; i < 4; i++)
#pragma unroll
        for (int j = 0; j < 8; j++)
#pragma unroll
            for (int e = 0; e < 4; e++) d[i][j][e] = 0.f;

    const int nk = K / 32;

    // stage loader: 2560 16-B chunks (Ah 512, Bh 1024, Bl 1024)
    auto issue = [&](int s, int buf) {
        const int koff = s * 32;
        const uint32_t stg = sbase + (uint32_t)buf * (STG3 * 2);
#pragma unroll
        for (int j = 0; j < 10; j++) {
            int idx = tid + j * 256;
            const __half* src;
            uint32_t off;
            int r;
            if (idx < 512)       { r = idx >> 2;          src = gAh; off = AH3; }
            else if (idx < 1536) { r = (idx - 512) >> 2;  src = gBh; off = BH3; }
            else                 { r = (idx - 1536) >> 2; src = gBl; off = BL3; }
            int c = idx & 3;
            int cs = c ^ ((r >> 1) & 3);
            cp_async16(stg + 2 * (off + r * 32 + cs * 8),
                       src + (size_t)r * K + koff + c * 8);
        }
        asm volatile("cp.async.commit_group;" ::: "memory");
    };

    issue(0, 0);
    if (nk > 1) issue(1, 1);
    if (nk > 2) issue(2, 2);

    for (int s = 0; s < nk; s++) {
        const int buf = s & 3;
        if (s + 2 < nk)      asm volatile("cp.async.wait_group 2;" ::: "memory");
        else if (s + 1 < nk) asm volatile("cp.async.wait_group 1;" ::: "memory");
        else                 asm volatile("cp.async.wait_group 0;" ::: "memory");
        __syncthreads();
        if (s + 3 < nk) issue(s + 3, (s + 3) & 3);

        const uint32_t stg = sbase + (uint32_t)buf * (STG3 * 2);

#pragma unroll
        for (int ks = 0; ks < 2; ks++) {
            const uint32_t LM = ks ? LM1 : LM0;
            uint32_t aH[4][4];
#pragma unroll
            for (int mt = 0; mt < 4; mt++) {
                uint32_t ab = stg + 2 * (AH3 + (warp_m * 64 + mt * 16) * 32 + LM);
                ldsm4(aH[mt][0], aH[mt][1], aH[mt][2], aH[mt][3], ab);
            }
#pragma unroll
            for (int ng = 0; ng < 4; ng++) {
                uint32_t bb = stg + 2 * ((warp_n * 64 + ng * 16) * 32 + LM);
                uint32_t bh0, bh1, bh2, bh3, bl0, bl1, bl2, bl3;
                ldsm4(bh0, bh1, bh2, bh3, bb + 2 * BH3);
                ldsm4(bl0, bl1, bl2, bl3, bb + 2 * BL3);
                // term 1 (Ah*Bh)
#pragma unroll
                for (int mt = 0; mt < 4; mt++) {
                    float* de = d[mt][2 * ng];
                    float* dc = d[mt][2 * ng + 1];
                    mma_fp16(de[0], de[1], de[2], de[3],
                             aH[mt][0], aH[mt][1], aH[mt][2], aH[mt][3], bh0, bh2);
                    mma_fp16(dc[0], dc[1], dc[2], dc[3],
                             aH[mt][0], aH[mt][1], aH[mt][2], aH[mt][3], bh1, bh3);
                }
                // term 2 (Ah*Bl)
#pragma unroll
                for (int mt = 0; mt < 4; mt++) {
                    float* de = d[mt][2 * ng];
                    float* dc = d[mt][2 * ng + 1];
                    mma_fp16(de[0], de[1], de[2], de[3],
                             aH[mt][0], aH[mt][1], aH[mt][2], aH[mt][3], bl0, bl2);
                    mma_fp16(dc[0], dc[1], dc[2], dc[3],
                             aH[mt][0], aH[mt][1], aH[mt][2], aH[mt][3], bl1, bl3);
                }
            }
        }
        __syncthreads();
    }

    // epilogue
#pragma unroll
    for (int mt = 0; mt < 4; mt++) {
        const int row = m0 + warp_m * 64 + mt * 16 + g;
#pragma unroll
        for (int nt = 0; nt < 8; nt++) {
            const int col = n0 + warp_n * 64 + nt * 8 + 2 * t;
            *(float2*)(C + (size_t)row * ldc + col) =
                make_float2(d[mt][nt][0], d[mt][nt][1]);
            *(float2*)(C + (size_t)(row + 8) * ldc + col) =
                make_float2(d[mt][nt][2], d[mt][nt][3]);
        }
    }
}

// ---------------------------------------------------------------------------
// RoPE in-place on Q (heads 0..31) and K (heads 32..39) inside g_qkv.
// ---------------------------------------------------------------------------
__global__ void rope_kernel(const float* __restrict__ cosb,
                            const float* __restrict__ sinb)
{
    int idx = blockIdx.x * blockDim.x + threadIdx.x;
    int p = idx & 63;
    int h = (idx >> 6) % 40;
    int s = idx / (64 * 40);
    float c  = cosb[s * 64 + p];
    float sn = sinb[s * 64 + p];
    float* base = g_qkv + (size_t)s * QKV_W
                + (h < NH ? h * HD : DIM + (h - NH) * HD) + 2 * p;
    float re = base[0], im = base[1];
    base[0] = re * c - im * sn;
    base[1] = re * sn + im * c;
}

// ---------------------------------------------------------------------------
// Tensor-core flash attention (fp16 x2).  Block = 128 q x 1 head,
// 8 warps x 16 rows.  S ≈ Qh*Kh + Qh*Kl;  O += Ph*Vh + Ph*Vl.
// smem: Qh[128][136] | Kh[64][136] | Kl | Vh | Vl   (fp16)
// ---------------------------------------------------------------------------
#define FS    136
#define QHO   0
#define KHO   17408
#define KLO   26112
#define VHO   34816
#define VLO   43520
#define FLASH_SMEM2 (52224 * 2)          /* 104448 B */

__global__ void __launch_bounds__(256, 1) flash_mma()
{
    extern __shared__ __half sb[];
    const uint32_t sb2 = smem_u32(sb);
    const int qt = blockIdx.x, h = blockIdx.y;
    const int q0 = qt * 128;
    const int kvh = h >> 2;
    const int tid = threadIdx.x;
    const int wid = tid >> 5, lane = tid & 31;
    const int g = lane >> 2, t = lane & 3;
    const int rmin = q0 + wid * 16;
    const uint32_t LM = (lane & 15) * FS + ((lane >> 4) << 3);

    // Q tile: hi only
    const float* qb = g_qkv + (size_t)q0 * QKV_W + h * HD;
#pragma unroll
    for (int p = 0; p < 16; p++) {
        int i = tid + p * 256;
        int r = i >> 5, c4 = i & 31;
        float4 v = *(const float4*)(qb + (size_t)r * QKV_W + c4 * 4);
        uint2 hh;
        conv4h(v, hh);
        *(uint2*)&sb[QHO + r * FS + c4 * 4] = hh;
    }

    float m0 = -1e30f, m1 = -1e30f, l0 = 0.f, l1 = 0.f;
    float o[16][4];
#pragma unroll
    for (int i = 0; i < 16; i++)
#pragma unroll
        for (int e = 0; e < 4; e++) o[i][e] = 0.f;

    const float scale = 0.08838834764831845f;
    const int nkt = 2 * (qt + 1);

    for (int kt = 0; kt < nkt; kt++) {
        __syncthreads();
        const float* kb = g_qkv + (size_t)(kt * 64) * QKV_W + DIM + kvh * HD;
        const float* vb = kb + KVD;
#pragma unroll
        for (int p = 0; p < 8; p++) {
            int i = tid + p * 256;
            int r = i >> 5, c4 = i & 31;
            int o2 = r * FS + c4 * 4;
            float4 kv = *(const float4*)(kb + (size_t)r * QKV_W + c4 * 4);
            uint2 hh, ll;
            split4h(kv, hh, ll);
            *(uint2*)&sb[KHO + o2] = hh;
            *(uint2*)&sb[KLO + o2] = ll;
            float4 vv = *(const float4*)(vb + (size_t)r * QKV_W + c4 * 4);
            split4h(vv, hh, ll);
            *(uint2*)&sb[VHO + o2] = hh;
            *(uint2*)&sb[VLO + o2] = ll;
        }
        __syncthreads();

        if (kt * 64 > rmin + 15) continue;

        float s[8][4];
#pragma unroll
        for (int i = 0; i < 8; i++)
#pragma unroll
            for (int e = 0; e < 4; e++) s[i][e] = 0.f;

#pragma unroll
        for (int ks = 0; ks < 8; ks++) {
            uint32_t qa = sb2 + 2 * (QHO + wid * 16 * FS + LM + ks * 16);
            uint32_t qh0, qh1, qh2, qh3;
            ldsm4(qh0, qh1, qh2, qh3, qa);
#pragma unroll
            for (int np = 0; np < 4; np++) {
                uint32_t ka = sb2 + 2 * (KHO + np * 16 * FS + LM + ks * 16);
                uint32_t kh0, kh1, kh2, kh3, kl0, kl1, kl2, kl3;
                ldsm4(kh0, kh1, kh2, kh3, ka);
                ldsm4(kl0, kl1, kl2, kl3, ka + 2 * (KLO - KHO));
                float* se = s[2 * np];
                float* so = s[2 * np + 1];
                mma_fp16(se[0], se[1], se[2], se[3], qh0, qh1, qh2, qh3, kh0, kh2);
                mma_fp16(so[0], so[1], so[2], so[3], qh0, qh1, qh2, qh3, kh1, kh3);
                mma_fp16(se[0], se[1], se[2], se[3], qh0, qh1, qh2, qh3, kl0, kl2);
                mma_fp16(so[0], so[1], so[2], so[3], qh0, qh1, qh2, qh3, kl1, kl3);
            }
        }

        const bool dm = (kt * 64 + 63) > rmin;
#pragma unroll
        for (int nt = 0; nt < 8; nt++) {
            int colb = kt * 64 + nt * 8 + 2 * t;
#pragma unroll
            for (int e = 0; e < 4; e++) {
                float v = s[nt][e] * scale;
                if (dm && (colb + (e & 1)) > (rmin + g + (e >> 1) * 8)) v = -1e30f;
                s[nt][e] = v;
            }
        }

        float rm0 = -1e30f, rm1 = -1e30f;
#pragma unroll
        for (int nt = 0; nt < 8; nt++) {
            rm0 = fmaxf(rm0, fmaxf(s[nt][0], s[nt][1]));
            rm1 = fmaxf(rm1, fmaxf(s[nt][2], s[nt][3]));
        }
        rm0 = fmaxf(rm0, __shfl_xor_sync(0xffffffffu, rm0, 1));
        rm0 = fmaxf(rm0, __shfl_xor_sync(0xffffffffu, rm0, 2));
        rm1 = fmaxf(rm1, __shfl_xor_sync(0xffffffffu, rm1, 1));
        rm1 = fmaxf(rm1, __shfl_xor_sync(0xffffffffu, rm1, 2));
        float mn0 = fmaxf(m0, rm0), mn1 = fmaxf(m1, rm1);
        float a0 = __expf(m0 - mn0), a1 = __expf(m1 - mn1);
        m0 = mn0; m1 = mn1;
        float ls0 = 0.f, ls1 = 0.f;
#pragma unroll
        for (int nt = 0; nt < 8; nt++) {
            s[nt][0] = __expf(s[nt][0] - mn0);
            s[nt][1] = __expf(s[nt][1] - mn0);
            s[nt][2] = __expf(s[nt][2] - mn1);
            s[nt][3] = __expf(s[nt][3] - mn1);
            ls0 += s[nt][0] + s[nt][1];
            ls1 += s[nt][2] + s[nt][3];
        }
        ls0 += __shfl_xor_sync(0xffffffffu, ls0, 1);
        ls0 += __shfl_xor_sync(0xffffffffu, ls0, 2);
        ls1 += __shfl_xor_sync(0xffffffffu, ls1, 1);
        ls1 += __shfl_xor_sync(0xffffffffu, ls1, 2);
        l0 = l0 * a0 + ls0;
        l1 = l1 * a1 + ls1;
#pragma unroll
        for (int nt = 0; nt < 16; nt++) {
            o[nt][0] *= a0; o[nt][1] *= a0;
            o[nt][2] *= a1; o[nt][3] *= a1;
        }

        // P -> fp16 A-fragments (hi only)
        uint32_t pah[4][4];
#pragma unroll
        for (int k2 = 0; k2 < 4; k2++) {
            pah[k2][0] = pack2h(s[2 * k2][0],     s[2 * k2][1]);
            pah[k2][1] = pack2h(s[2 * k2][2],     s[2 * k2][3]);
            pah[k2][2] = pack2h(s[2 * k2 + 1][0], s[2 * k2 + 1][1]);
            pah[k2][3] = pack2h(s[2 * k2 + 1][2], s[2 * k2 + 1][3]);
        }

#pragma unroll
        for (int k2 = 0; k2 < 4; k2++) {
#pragma unroll
            for (int np = 0; np < 8; np++) {
                uint32_t va = sb2 + 2 * (VHO + k2 * 16 * FS + LM + np * 16);
                uint32_t vh0, vh1, vh2, vh3, vl0, vl1, vl2, vl3;
                ldsm4t(vh0, vh1, vh2, vh3, va);
                ldsm4t(vl0, vl1, vl2, vl3, va + 2 * (VLO - VHO));
                float* oe = o[2 * np];
                float* oo = o[2 * np + 1];
                mma_fp16(oe[0], oe[1], oe[2], oe[3],
                         pah[k2][0], pah[k2][1], pah[k2][2], pah[k2][3], vh0, vh1);
                mma_fp16(oo[0], oo[1], oo[2], oo[3],
                         pah[k2][0], pah[k2][1], pah[k2][2], pah[k2][3], vh2, vh3);
                mma_fp16(oe[0], oe[1], oe[2], oe[3],
                         pah[k2][0], pah[k2][1], pah[k2][2], pah[k2][3], vl0, vl1);
                mma_fp16(oo[0], oo[1], oo[2], oo[3],
                         pah[k2][0], pah[k2][1], pah[k2][2], pah[k2][3], vl2, vl3);
            }
        }
    }

    // epilogue: normalize, write fp16 (A-side of WO GEMM needs hi only)
    float i0 = 1.f / l0, i1 = 1.f / l1;
    __half* oh0 = g_ah + (size_t)(rmin + g) * DIM + h * HD;
    __half* oh1 = g_ah + (size_t)(rmin + g + 8) * DIM + h * HD;
#pragma unroll
    for (int nt = 0; nt < 16; nt++) {
        int col = nt * 8 + 2 * t;
        *(uint32_t*)(oh0 + col) = pack2h(o[nt][0] * i0, o[nt][1] * i0);
        *(uint32_t*)(oh1 + col) = pack2h(o[nt][2] * i1, o[nt][3] * i1);
    }
}

// ---------------------------------------------------------------------------
extern "C" void kernel_launch(void* const* d_in, const int* in_sizes, int n_in,
                              void* d_out, int out_size)
{
    const float* x  = (const float*)d_in[0];
    const float* wq = (const float*)d_in[1];
    const float* wk = (const float*)d_in[2];
    const float* wv = (const float*)d_in[3];
    const float* wo = (const float*)d_in[4];
    const float* fc = (const float*)d_in[7];
    const float* fs = (const float*)d_in[8];
    float* out = (float*)d_out;
    (void)in_sizes; (void)n_in; (void)out_size;

    static float* qkv = nullptr;
    static __half *xh, *wAh, *wAl, *woh, *wol, *ah;
    if (!qkv) {   // first call is the uncaptured correctness run
        cudaGetSymbolAddress((void**)&qkv, g_qkv);
        cudaGetSymbolAddress((void**)&xh, g_xh);
        cudaGetSymbolAddress((void**)&wAh, g_wAh); cudaGetSymbolAddress((void**)&wAl, g_wAl);
        cudaGetSymbolAddress((void**)&woh, g_woh); cudaGetSymbolAddress((void**)&wol, g_wol);
        cudaGetSymbolAddress((void**)&ah, g_ah);
        cudaFuncSetAttribute(gemm_mma2,
                             cudaFuncAttributeMaxDynamicSharedMemorySize, GEMM_SMEM);
        cudaFuncSetAttribute(flash_mma,
                             cudaFuncAttributeMaxDynamicSharedMemorySize, FLASH_SMEM2);
    }

    // fp32 -> fp16 conversions (x hi-only; weights hi+lo, wq|wk|wv fused)
    conv_kernel<<<(SEQ * DIM / 4 + 255) / 256, 256>>>(x, xh, SEQ * DIM / 4);
    split_kernel<<<(DIM * DIM / 4 + 255) / 256, 256>>>(wq, wAh, wAl, DIM * DIM / 4);
    split_kernel<<<(KVD * DIM / 4 + 255) / 256, 256>>>(
        wk, wAh + (size_t)DIM * DIM, wAl + (size_t)DIM * DIM, KVD * DIM / 4);
    split_kernel<<<(KVD * DIM / 4 + 255) / 256, 256>>>(
        wv, wAh + (size_t)(DIM + KVD) * DIM, wAl + (size_t)(DIM + KVD) * DIM, KVD * DIM / 4);
    split_kernel<<<(DIM * DIM / 4 + 255) / 256, 256>>>(wo, woh, wol, DIM * DIM / 4);

    // Fused QKV projection (one GEMM, N = 6144) -> g_qkv [S, 6144]
    gemm_mma2<<<dim3(QKV_W / 256, SEQ / 128), 256, GEMM_SMEM>>>(
        xh, wAh, wAl, qkv, QKV_W, DIM);

    // RoPE on Q + K in place
    rope_kernel<<<SEQ * 40 * 64 / 256, 256>>>(fc, fs);

    // Causal GQA flash attention -> g_ah (fp16)
    flash_mma<<<dim3(SEQ / 128, NH), 256, FLASH_SMEM2>>>();

    // Output projection
    gemm_mma2<<<dim3(DIM / 256, SEQ / 128), 256, GEMM_SMEM>>>(
        ah, woh, wol, out, DIM, DIM);
}

// round 11
// speedup vs baseline: 3.6811x; 1.6840x over previous
#include <cuda_runtime.h>
#include <cuda_fp16.h>
#include <math.h>
#include <cstdint>

#define SEQ   2048
#define DIM   4096
#define NH    32
#define NKV   8
#define HD    128
#define KVD   (NKV * HD)             /* 1024 */
#define QKV_W (DIM + 2 * KVD)        /* 6144: [q 4096 | k 1024 | v 1024] per row */

// ---------------------------------------------------------------------------
// Scratch (__device__ globals — the sanctioned allocation mechanism)
// ---------------------------------------------------------------------------
__device__ float g_qkv[SEQ * QKV_W];
__device__ __half g_xh[SEQ * DIM];
__device__ __half g_wAh[QKV_W * DIM];      // wq|wk|wv fused
__device__ __half g_woh[DIM * DIM];
__device__ __half g_ah[SEQ * DIM];         // flash output (fp16)

// ---------------------------------------------------------------------------
// helpers
// ---------------------------------------------------------------------------
__device__ __forceinline__ uint32_t smem_u32(const void* p) {
    uint32_t a;
    asm("{ .reg .u64 t; cvta.to.shared.u64 t, %1; cvt.u32.u64 %0, t; }"
        : "=r"(a) : "l"(p));
    return a;
}
__device__ __forceinline__ void cp_async16(uint32_t dst, const void* src) {
    asm volatile("cp.async.cg.shared.global [%0], [%1], 16;"
                 :: "r"(dst), "l"(src));
}
__device__ __forceinline__ void mma_fp16(float& d0, float& d1, float& d2, float& d3,
                                         uint32_t a0, uint32_t a1, uint32_t a2, uint32_t a3,
                                         uint32_t b0, uint32_t b1)
{
    asm volatile(
        "mma.sync.aligned.m16n8k16.row.col.f32.f16.f16.f32 "
        "{%0,%1,%2,%3}, {%4,%5,%6,%7}, {%8,%9}, {%0,%1,%2,%3};"
        : "+f"(d0), "+f"(d1), "+f"(d2), "+f"(d3)
        : "r"(a0), "r"(a1), "r"(a2), "r"(a3), "r"(b0), "r"(b1));
}
__device__ __forceinline__ void ldsm4(uint32_t& r0, uint32_t& r1, uint32_t& r2,
                                      uint32_t& r3, uint32_t a)
{
    asm volatile("ldmatrix.sync.aligned.m8n8.x4.shared.b16 {%0,%1,%2,%3}, [%4];"
                 : "=r"(r0), "=r"(r1), "=r"(r2), "=r"(r3) : "r"(a));
}
__device__ __forceinline__ void ldsm4t(uint32_t& r0, uint32_t& r1, uint32_t& r2,
                                       uint32_t& r3, uint32_t a)
{
    asm volatile("ldmatrix.sync.aligned.m8n8.x4.trans.shared.b16 {%0,%1,%2,%3}, [%4];"
                 : "=r"(r0), "=r"(r1), "=r"(r2), "=r"(r3) : "r"(a));
}
__device__ __forceinline__ uint32_t pack2h(float x, float y) {
    __half2 hv = __halves2half2(__float2half_rn(x), __float2half_rn(y));
    return *(uint32_t*)&hv;
}
__device__ __forceinline__ void conv4h(float4 v, uint2& h) {
    __half2 ha = __halves2half2(__float2half_rn(v.x), __float2half_rn(v.y));
    __half2 hb = __halves2half2(__float2half_rn(v.z), __float2half_rn(v.w));
    h = make_uint2(*(uint32_t*)&ha, *(uint32_t*)&hb);
}

// ---------------------------------------------------------------------------
// fp32 -> fp16 convert (vectorized x4)
// ---------------------------------------------------------------------------
__global__ void conv_kernel(const float* __restrict__ src,
                            __half* __restrict__ hi, int n4)
{
    int i = blockIdx.x * blockDim.x + threadIdx.x;
    if (i >= n4) return;
    float4 v = ((const float4*)src)[i];
    uint2 h;
    conv4h(v, h);
    ((uint2*)hi)[i] = h;
}

// ---------------------------------------------------------------------------
// HMMA GEMM (pure fp16): C[M,N] = A[M,K]*B[N,K]^T, fp32 accum.
// 128x256 block tile, warp 64x64 (2x4), BK=32, 4-stage cp.async, XOR swizzle.
// Stage = Ah(128) | Bh(256) rows of 64 B.
// ---------------------------------------------------------------------------
#define AH3   0
#define BH3   (128 * 32)                 /* 4096  halfs */
#define STG3  (BH3 + 256 * 32)           /* 12288 halfs = 24576 B */
#define GEMM_SMEM (4 * STG3 * 2)         /* 98304 B */

__global__ void __launch_bounds__(256, 1) gemm_mma2(
    const __half* __restrict__ Ah,
    const __half* __restrict__ Bh,
    float* __restrict__ C, int ldc, int K)
{
    extern __shared__ __half sm3[];
    const uint32_t sbase = smem_u32(sm3);
    const int tid = threadIdx.x;
    const int wid = tid >> 5, lane = tid & 31;
    const int warp_m = wid & 1, warp_n = wid >> 1;      // 2 x 4 warp grid
    const int g = lane >> 2, t = lane & 3;
    const int m0 = blockIdx.y * 128, n0 = blockIdx.x * 256;

    const int rl = lane & 15;
    const int sw = (rl >> 1) & 3;
    const int ch = lane >> 4;
    const uint32_t LM0 = rl * 32 + (((ch + 0) ^ sw) << 3);
    const uint32_t LM1 = rl * 32 + (((ch + 2) ^ sw) << 3);

    const __half* gAh = Ah + (size_t)m0 * K;
    const __half* gBh = Bh + (size_t)n0 * K;

    float d[4][8][4];
#pragma unroll
    for (int i = 0; i < 4; i++)
#pragma unroll
        for (int j = 0; j < 8; j++)
#pragma unroll
            for (int e = 0; e < 4; e++) d[i][j][e] = 0.f;

    const int nk = K / 32;

    // stage loader: 1536 16-B chunks (Ah 512, Bh 1024)
    auto issue = [&](int s, int buf) {
        const int koff = s * 32;
        const uint32_t stg = sbase + (uint32_t)buf * (STG3 * 2);
#pragma unroll
        for (int j = 0; j < 6; j++) {
            int idx = tid + j * 256;
            const __half* src;
            uint32_t off;
            int r;
            if (idx < 512) { r = idx >> 2;         src = gAh; off = AH3; }
            else           { r = (idx - 512) >> 2; src = gBh; off = BH3; }
            int c = idx & 3;
            int cs = c ^ ((r >> 1) & 3);
            cp_async16(stg + 2 * (off + r * 32 + cs * 8),
                       src + (size_t)r * K + koff + c * 8);
        }
        asm volatile("cp.async.commit_group;" ::: "memory");
    };

    issue(0, 0);
    if (nk > 1) issue(1, 1);
    if (nk > 2) issue(2, 2);

    for (int s = 0; s < nk; s++) {
        const int buf = s & 3;
        if (s + 2 < nk)      asm volatile("cp.async.wait_group 2;" ::: "memory");
        else if (s + 1 < nk) asm volatile("cp.async.wait_group 1;" ::: "memory");
        else                 asm volatile("cp.async.wait_group 0;" ::: "memory");
        __syncthreads();
        if (s + 3 < nk) issue(s + 3, (s + 3) & 3);

        const uint32_t stg = sbase + (uint32_t)buf * (STG3 * 2);

#pragma unroll
        for (int ks = 0; ks < 2; ks++) {
            const uint32_t LM = ks ? LM1 : LM0;
            uint32_t aH[4][4];
#pragma unroll
            for (int mt = 0; mt < 4; mt++) {
                uint32_t ab = stg + 2 * (AH3 + (warp_m * 64 + mt * 16) * 32 + LM);
                ldsm4(aH[mt][0], aH[mt][1], aH[mt][2], aH[mt][3], ab);
            }
#pragma unroll
            for (int ng = 0; ng < 4; ng++) {
                uint32_t bb = stg + 2 * (BH3 + (warp_n * 64 + ng * 16) * 32 + LM);
                uint32_t bh0, bh1, bh2, bh3;
                ldsm4(bh0, bh1, bh2, bh3, bb);
#pragma unroll
                for (int mt = 0; mt < 4; mt++) {
                    float* de = d[mt][2 * ng];
                    float* dc = d[mt][2 * ng + 1];
                    mma_fp16(de[0], de[1], de[2], de[3],
                             aH[mt][0], aH[mt][1], aH[mt][2], aH[mt][3], bh0, bh2);
                    mma_fp16(dc[0], dc[1], dc[2], dc[3],
                             aH[mt][0], aH[mt][1], aH[mt][2], aH[mt][3], bh1, bh3);
                }
            }
        }
        __syncthreads();
    }

    // epilogue
#pragma unroll
    for (int mt = 0; mt < 4; mt++) {
        const int row = m0 + warp_m * 64 + mt * 16 + g;
#pragma unroll
        for (int nt = 0; nt < 8; nt++) {
            const int col = n0 + warp_n * 64 + nt * 8 + 2 * t;
            *(float2*)(C + (size_t)row * ldc + col) =
                make_float2(d[mt][nt][0], d[mt][nt][1]);
            *(float2*)(C + (size_t)(row + 8) * ldc + col) =
                make_float2(d[mt][nt][2], d[mt][nt][3]);
        }
    }
}

// ---------------------------------------------------------------------------
// RoPE in-place on Q (heads 0..31) and K (heads 32..39) inside g_qkv.
// ---------------------------------------------------------------------------
__global__ void rope_kernel(const float* __restrict__ cosb,
                            const float* __restrict__ sinb)
{
    int idx = blockIdx.x * blockDim.x + threadIdx.x;
    int p = idx & 63;
    int h = (idx >> 6) % 40;
    int s = idx / (64 * 40);
    float c  = cosb[s * 64 + p];
    float sn = sinb[s * 64 + p];
    float* base = g_qkv + (size_t)s * QKV_W
                + (h < NH ? h * HD : DIM + (h - NH) * HD) + 2 * p;
    float re = base[0], im = base[1];
    base[0] = re * c - im * sn;
    base[1] = re * sn + im * c;
}

// ---------------------------------------------------------------------------
// Tensor-core flash attention (pure fp16 operands, fp32 accum).
// Block = 128 q x 1 head, 8 warps x 16 rows.
// Longest-first scheduling: qt = gridDim.x-1-blockIdx.x.
// smem: Qh[128][136] | Kh[64][136] | Vh[64][136]
// ---------------------------------------------------------------------------
#define FS    136
#define QHO   0
#define KHO   17408
#define VHO   26112
#define FLASH_SMEM2 (34816 * 2)          /* 69632 B */

__global__ void __launch_bounds__(256, 1) flash_mma()
{
    extern __shared__ __half sb[];
    const uint32_t sb2 = smem_u32(sb);
    const int qt = (int)gridDim.x - 1 - (int)blockIdx.x;  // longest tiles first
    const int h = blockIdx.y;
    const int q0 = qt * 128;
    const int kvh = h >> 2;
    const int tid = threadIdx.x;
    const int wid = tid >> 5, lane = tid & 31;
    const int g = lane >> 2, t = lane & 3;
    const int rmin = q0 + wid * 16;
    const uint32_t LM = (lane & 15) * FS + ((lane >> 4) << 3);

    // Q tile (fp16)
    const float* qb = g_qkv + (size_t)q0 * QKV_W + h * HD;
#pragma unroll
    for (int p = 0; p < 16; p++) {
        int i = tid + p * 256;
        int r = i >> 5, c4 = i & 31;
        float4 v = *(const float4*)(qb + (size_t)r * QKV_W + c4 * 4);
        uint2 hh;
        conv4h(v, hh);
        *(uint2*)&sb[QHO + r * FS + c4 * 4] = hh;
    }

    float m0 = -1e30f, m1 = -1e30f, l0 = 0.f, l1 = 0.f;
    float o[16][4];
#pragma unroll
    for (int i = 0; i < 16; i++)
#pragma unroll
        for (int e = 0; e < 4; e++) o[i][e] = 0.f;

    const float scale = 0.08838834764831845f;
    const int nkt = 2 * (qt + 1);

    for (int kt = 0; kt < nkt; kt++) {
        __syncthreads();
        const float* kb = g_qkv + (size_t)(kt * 64) * QKV_W + DIM + kvh * HD;
        const float* vb = kb + KVD;
#pragma unroll
        for (int p = 0; p < 8; p++) {
            int i = tid + p * 256;
            int r = i >> 5, c4 = i & 31;
            int o2 = r * FS + c4 * 4;
            float4 kv = *(const float4*)(kb + (size_t)r * QKV_W + c4 * 4);
            uint2 hh;
            conv4h(kv, hh);
            *(uint2*)&sb[KHO + o2] = hh;
            float4 vv = *(const float4*)(vb + (size_t)r * QKV_W + c4 * 4);
            conv4h(vv, hh);
            *(uint2*)&sb[VHO + o2] = hh;
        }
        __syncthreads();

        if (kt * 64 > rmin + 15) continue;

        float s[8][4];
#pragma unroll
        for (int i = 0; i < 8; i++)
#pragma unroll
            for (int e = 0; e < 4; e++) s[i][e] = 0.f;

#pragma unroll
        for (int ks = 0; ks < 8; ks++) {
            uint32_t qa = sb2 + 2 * (QHO + wid * 16 * FS + LM + ks * 16);
            uint32_t qh0, qh1, qh2, qh3;
            ldsm4(qh0, qh1, qh2, qh3, qa);
#pragma unroll
            for (int np = 0; np < 4; np++) {
                uint32_t ka = sb2 + 2 * (KHO + np * 16 * FS + LM + ks * 16);
                uint32_t kh0, kh1, kh2, kh3;
                ldsm4(kh0, kh1, kh2, kh3, ka);
                float* se = s[2 * np];
                float* so = s[2 * np + 1];
                mma_fp16(se[0], se[1], se[2], se[3], qh0, qh1, qh2, qh3, kh0, kh2);
                mma_fp16(so[0], so[1], so[2], so[3], qh0, qh1, qh2, qh3, kh1, kh3);
            }
        }

        const bool dm = (kt * 64 + 63) > rmin;
#pragma unroll
        for (int nt = 0; nt < 8; nt++) {
            int colb = kt * 64 + nt * 8 + 2 * t;
#pragma unroll
            for (int e = 0; e < 4; e++) {
                float v = s[nt][e] * scale;
                if (dm && (colb + (e & 1)) > (rmin + g + (e >> 1) * 8)) v = -1e30f;
                s[nt][e] = v;
            }
        }

        float rm0 = -1e30f, rm1 = -1e30f;
#pragma unroll
        for (int nt = 0; nt < 8; nt++) {
            rm0 = fmaxf(rm0, fmaxf(s[nt][0], s[nt][1]));
            rm1 = fmaxf(rm1, fmaxf(s[nt][2], s[nt][3]));
        }
        rm0 = fmaxf(rm0, __shfl_xor_sync(0xffffffffu, rm0, 1));
        rm0 = fmaxf(rm0, __shfl_xor_sync(0xffffffffu, rm0, 2));
        rm1 = fmaxf(rm1, __shfl_xor_sync(0xffffffffu, rm1, 1));
        rm1 = fmaxf(rm1, __shfl_xor_sync(0xffffffffu, rm1, 2));
        float mn0 = fmaxf(m0, rm0), mn1 = fmaxf(m1, rm1);
        float a0 = __expf(m0 - mn0), a1 = __expf(m1 - mn1);
        m0 = mn0; m1 = mn1;
        float ls0 = 0.f, ls1 = 0.f;
#pragma unroll
        for (int nt = 0; nt < 8; nt++) {
            s[nt][0] = __expf(s[nt][0] - mn0);
            s[nt][1] = __expf(s[nt][1] - mn0);
            s[nt][2] = __expf(s[nt][2] - mn1);
            s[nt][3] = __expf(s[nt][3] - mn1);
            ls0 += s[nt][0] + s[nt][1];
            ls1 += s[nt][2] + s[nt][3];
        }
        ls0 += __shfl_xor_sync(0xffffffffu, ls0, 1);
        ls0 += __shfl_xor_sync(0xffffffffu, ls0, 2);
        ls1 += __shfl_xor_sync(0xffffffffu, ls1, 1);
        ls1 += __shfl_xor_sync(0xffffffffu, ls1, 2);
        l0 = l0 * a0 + ls0;
        l1 = l1 * a1 + ls1;
#pragma unroll
        for (int nt = 0; nt < 16; nt++) {
            o[nt][0] *= a0; o[nt][1] *= a0;
            o[nt][2] *= a1; o[nt][3] *= a1;
        }

        // P -> fp16 A-fragments
        uint32_t pah[4][4];
#pragma unroll
        for (int k2 = 0; k2 < 4; k2++) {
            pah[k2][0] = pack2h(s[2 * k2][0],     s[2 * k2][1]);
            pah[k2][1] = pack2h(s[2 * k2][2],     s[2 * k2][3]);
            pah[k2][2] = pack2h(s[2 * k2 + 1][0], s[2 * k2 + 1][1]);
            pah[k2][3] = pack2h(s[2 * k2 + 1][2], s[2 * k2 + 1][3]);
        }

#pragma unroll
        for (int k2 = 0; k2 < 4; k2++) {
#pragma unroll
            for (int np = 0; np < 8; np++) {
                uint32_t va = sb2 + 2 * (VHO + k2 * 16 * FS + LM + np * 16);
                uint32_t vh0, vh1, vh2, vh3;
                ldsm4t(vh0, vh1, vh2, vh3, va);
                float* oe = o[2 * np];
                float* oo = o[2 * np + 1];
                mma_fp16(oe[0], oe[1], oe[2], oe[3],
                         pah[k2][0], pah[k2][1], pah[k2][2], pah[k2][3], vh0, vh1);
                mma_fp16(oo[0], oo[1], oo[2], oo[3],
                         pah[k2][0], pah[k2][1], pah[k2][2], pah[k2][3], vh2, vh3);
            }
        }
    }

    // epilogue: normalize, write fp16 (A-side of WO GEMM)
    float i0 = 1.f / l0, i1 = 1.f / l1;
    __half* oh0 = g_ah + (size_t)(rmin + g) * DIM + h * HD;
    __half* oh1 = g_ah + (size_t)(rmin + g + 8) * DIM + h * HD;
#pragma unroll
    for (int nt = 0; nt < 16; nt++) {
        int col = nt * 8 + 2 * t;
        *(uint32_t*)(oh0 + col) = pack2h(o[nt][0] * i0, o[nt][1] * i0);
        *(uint32_t*)(oh1 + col) = pack2h(o[nt][2] * i1, o[nt][3] * i1);
    }
}

// ---------------------------------------------------------------------------
extern "C" void kernel_launch(void* const* d_in, const int* in_sizes, int n_in,
                              void* d_out, int out_size)
{
    const float* x  = (const float*)d_in[0];
    const float* wq = (const float*)d_in[1];
    const float* wk = (const float*)d_in[2];
    const float* wv = (const float*)d_in[3];
    const float* wo = (const float*)d_in[4];
    const float* fc = (const float*)d_in[7];
    const float* fs = (const float*)d_in[8];
    float* out = (float*)d_out;
    (void)in_sizes; (void)n_in; (void)out_size;

    static float* qkv = nullptr;
    static __half *xh, *wAh, *woh, *ah;
    if (!qkv) {   // first call is the uncaptured correctness run
        cudaGetSymbolAddress((void**)&qkv, g_qkv);
        cudaGetSymbolAddress((void**)&xh, g_xh);
        cudaGetSymbolAddress((void**)&wAh, g_wAh);
        cudaGetSymbolAddress((void**)&woh, g_woh);
        cudaGetSymbolAddress((void**)&ah, g_ah);
        cudaFuncSetAttribute(gemm_mma2,
                             cudaFuncAttributeMaxDynamicSharedMemorySize, GEMM_SMEM);
        cudaFuncSetAttribute(flash_mma,
                             cudaFuncAttributeMaxDynamicSharedMemorySize, FLASH_SMEM2);
    }

    // fp32 -> fp16 conversions (wq|wk|wv fused into one [6144 x 4096] buffer)
    conv_kernel<<<(SEQ * DIM / 4 + 255) / 256, 256>>>(x, xh, SEQ * DIM / 4);
    conv_kernel<<<(DIM * DIM / 4 + 255) / 256, 256>>>(wq, wAh, DIM * DIM / 4);
    conv_kernel<<<(KVD * DIM / 4 + 255) / 256, 256>>>(
        wk, wAh + (size_t)DIM * DIM, KVD * DIM / 4);
    conv_kernel<<<(KVD * DIM / 4 + 255) / 256, 256>>>(
        wv, wAh + (size_t)(DIM + KVD) * DIM, KVD * DIM / 4);
    conv_kernel<<<(DIM * DIM / 4 + 255) / 256, 256>>>(wo, woh, DIM * DIM / 4);

    // Fused QKV projection (one GEMM, N = 6144) -> g_qkv [S, 6144]
    gemm_mma2<<<dim3(QKV_W / 256, SEQ / 128), 256, GEMM_SMEM>>>(
        xh, wAh, qkv, QKV_W, DIM);

    // RoPE on Q + K in place
    rope_kernel<<<SEQ * 40 * 64 / 256, 256>>>(fc, fs);

    // Causal GQA flash attention -> g_ah (fp16)
    flash_mma<<<dim3(SEQ / 128, NH), 256, FLASH_SMEM2>>>();

    // Output projection
    gemm_mma2<<<dim3(DIM / 256, SEQ / 128), 256, GEMM_SMEM>>>(
        ah, woh, out, DIM, DIM);
}

// round 12
// speedup vs baseline: 3.7665x; 1.0232x over previous
#include <cuda_runtime.h>
#include <cuda_fp16.h>
#include <math.h>
#include <cstdint>

#define SEQ   2048
#define DIM   4096
#define NH    32
#define NKV   8
#define HD    128
#define KVD   (NKV * HD)             /* 1024 */
#define QKV_W (DIM + 2 * KVD)        /* 6144: [q 4096 | k 1024 | v 1024] per row */

// ---------------------------------------------------------------------------
// Scratch (__device__ globals — the sanctioned allocation mechanism)
// ---------------------------------------------------------------------------
__device__ __half g_qkvh[SEQ * QKV_W];     // fp16 qkv, RoPE pre-applied
__device__ __half g_xh[SEQ * DIM];
__device__ __half g_wAh[QKV_W * DIM];      // wq|wk|wv fused
__device__ __half g_woh[DIM * DIM];
__device__ __half g_ah[SEQ * DIM];         // flash output (fp16)

// ---------------------------------------------------------------------------
// helpers
// ---------------------------------------------------------------------------
__device__ __forceinline__ uint32_t smem_u32(const void* p) {
    uint32_t a;
    asm("{ .reg .u64 t; cvta.to.shared.u64 t, %1; cvt.u32.u64 %0, t; }"
        : "=r"(a) : "l"(p));
    return a;
}
__device__ __forceinline__ void cp_async16(uint32_t dst, const void* src) {
    asm volatile("cp.async.cg.shared.global [%0], [%1], 16;"
                 :: "r"(dst), "l"(src));
}
__device__ __forceinline__ void mma_fp16(float& d0, float& d1, float& d2, float& d3,
                                         uint32_t a0, uint32_t a1, uint32_t a2, uint32_t a3,
                                         uint32_t b0, uint32_t b1)
{
    asm volatile(
        "mma.sync.aligned.m16n8k16.row.col.f32.f16.f16.f32 "
        "{%0,%1,%2,%3}, {%4,%5,%6,%7}, {%8,%9}, {%0,%1,%2,%3};"
        : "+f"(d0), "+f"(d1), "+f"(d2), "+f"(d3)
        : "r"(a0), "r"(a1), "r"(a2), "r"(a3), "r"(b0), "r"(b1));
}
__device__ __forceinline__ void ldsm4(uint32_t& r0, uint32_t& r1, uint32_t& r2,
                                      uint32_t& r3, uint32_t a)
{
    asm volatile("ldmatrix.sync.aligned.m8n8.x4.shared.b16 {%0,%1,%2,%3}, [%4];"
                 : "=r"(r0), "=r"(r1), "=r"(r2), "=r"(r3) : "r"(a));
}
__device__ __forceinline__ void ldsm4t(uint32_t& r0, uint32_t& r1, uint32_t& r2,
                                       uint32_t& r3, uint32_t a)
{
    asm volatile("ldmatrix.sync.aligned.m8n8.x4.trans.shared.b16 {%0,%1,%2,%3}, [%4];"
                 : "=r"(r0), "=r"(r1), "=r"(r2), "=r"(r3) : "r"(a));
}
__device__ __forceinline__ uint32_t pack2h(float x, float y) {
    __half2 hv = __halves2half2(__float2half_rn(x), __float2half_rn(y));
    return *(uint32_t*)&hv;
}
__device__ __forceinline__ void conv4h(float4 v, uint2& h) {
    __half2 ha = __halves2half2(__float2half_rn(v.x), __float2half_rn(v.y));
    __half2 hb = __halves2half2(__float2half_rn(v.z), __float2half_rn(v.w));
    h = make_uint2(*(uint32_t*)&ha, *(uint32_t*)&hb);
}

// ---------------------------------------------------------------------------
// fp32 -> fp16 convert (vectorized x4)
// ---------------------------------------------------------------------------
__global__ void conv_kernel(const float* __restrict__ src,
                            __half* __restrict__ hi, int n4)
{
    int i = blockIdx.x * blockDim.x + threadIdx.x;
    if (i >= n4) return;
    float4 v = ((const float4*)src)[i];
    uint2 h;
    conv4h(v, h);
    ((uint2*)hi)[i] = h;
}

// ---------------------------------------------------------------------------
// HMMA GEMM (pure fp16): C = A[M,K]*B[N,K]^T, fp32 accum.
// 128x256 tile, warp 64x64 (2x4), BK=32, 4-stage cp.async, XOR swizzle.
// ROPE=true: apply rotary embedding to Q/K columns and write fp16 (g_qkvh).
// ROPE=false: write fp32.
// ---------------------------------------------------------------------------
#define AH3   0
#define BH3   (128 * 32)                 /* 4096  halfs */
#define STG3  (BH3 + 256 * 32)           /* 12288 halfs = 24576 B */
#define GEMM_SMEM (4 * STG3 * 2)         /* 98304 B */

template <bool ROPE>
__global__ void __launch_bounds__(256, 1) gemm_mma2(
    const __half* __restrict__ Ah,
    const __half* __restrict__ Bh,
    float* __restrict__ Cf, __half* __restrict__ Ch,
    const float* __restrict__ fc, const float* __restrict__ fs,
    int ldc, int K)
{
    extern __shared__ __half sm3[];
    const uint32_t sbase = smem_u32(sm3);
    const int tid = threadIdx.x;
    const int wid = tid >> 5, lane = tid & 31;
    const int warp_m = wid & 1, warp_n = wid >> 1;      // 2 x 4 warp grid
    const int g = lane >> 2, t = lane & 3;
    const int m0 = blockIdx.y * 128, n0 = blockIdx.x * 256;

    const int rl = lane & 15;
    const int sw = (rl >> 1) & 3;
    const int ch = lane >> 4;
    const uint32_t LM0 = rl * 32 + (((ch + 0) ^ sw) << 3);
    const uint32_t LM1 = rl * 32 + (((ch + 2) ^ sw) << 3);

    const __half* gAh = Ah + (size_t)m0 * K;
    const __half* gBh = Bh + (size_t)n0 * K;

    float d[4][8][4];
#pragma unroll
    for (int i = 0; i < 4; i++)
#pragma unroll
        for (int j = 0; j < 8; j++)
#pragma unroll
            for (int e = 0; e < 4; e++) d[i][j][e] = 0.f;

    const int nk = K / 32;

    auto issue = [&](int s, int buf) {
        const int koff = s * 32;
        const uint32_t stg = sbase + (uint32_t)buf * (STG3 * 2);
#pragma unroll
        for (int j = 0; j < 6; j++) {
            int idx = tid + j * 256;
            const __half* src;
            uint32_t off;
            int r;
            if (idx < 512) { r = idx >> 2;         src = gAh; off = AH3; }
            else           { r = (idx - 512) >> 2; src = gBh; off = BH3; }
            int c = idx & 3;
            int cs = c ^ ((r >> 1) & 3);
            cp_async16(stg + 2 * (off + r * 32 + cs * 8),
                       src + (size_t)r * K + koff + c * 8);
        }
        asm volatile("cp.async.commit_group;" ::: "memory");
    };

    issue(0, 0);
    if (nk > 1) issue(1, 1);
    if (nk > 2) issue(2, 2);

    for (int s = 0; s < nk; s++) {
        const int buf = s & 3;
        if (s + 2 < nk)      asm volatile("cp.async.wait_group 2;" ::: "memory");
        else if (s + 1 < nk) asm volatile("cp.async.wait_group 1;" ::: "memory");
        else                 asm volatile("cp.async.wait_group 0;" ::: "memory");
        __syncthreads();
        if (s + 3 < nk) issue(s + 3, (s + 3) & 3);

        const uint32_t stg = sbase + (uint32_t)buf * (STG3 * 2);

#pragma unroll
        for (int ks = 0; ks < 2; ks++) {
            const uint32_t LM = ks ? LM1 : LM0;
            uint32_t aH[4][4];
#pragma unroll
            for (int mt = 0; mt < 4; mt++) {
                uint32_t ab = stg + 2 * (AH3 + (warp_m * 64 + mt * 16) * 32 + LM);
                ldsm4(aH[mt][0], aH[mt][1], aH[mt][2], aH[mt][3], ab);
            }
#pragma unroll
            for (int ng = 0; ng < 4; ng++) {
                uint32_t bb = stg + 2 * (BH3 + (warp_n * 64 + ng * 16) * 32 + LM);
                uint32_t bh0, bh1, bh2, bh3;
                ldsm4(bh0, bh1, bh2, bh3, bb);
#pragma unroll
                for (int mt = 0; mt < 4; mt++) {
                    float* de = d[mt][2 * ng];
                    float* dc = d[mt][2 * ng + 1];
                    mma_fp16(de[0], de[1], de[2], de[3],
                             aH[mt][0], aH[mt][1], aH[mt][2], aH[mt][3], bh0, bh2);
                    mma_fp16(dc[0], dc[1], dc[2], dc[3],
                             aH[mt][0], aH[mt][1], aH[mt][2], aH[mt][3], bh1, bh3);
                }
            }
        }
        __syncthreads();
    }

    // epilogue
#pragma unroll
    for (int mt = 0; mt < 4; mt++) {
        const int row = m0 + warp_m * 64 + mt * 16 + g;
#pragma unroll
        for (int nt = 0; nt < 8; nt++) {
            const int col = n0 + warp_n * 64 + nt * 8 + 2 * t;
            if (ROPE) {
                float v0 = d[mt][nt][0], v1 = d[mt][nt][1];
                float v2 = d[mt][nt][2], v3 = d[mt][nt][3];
                if (col < DIM + KVD) {   // Q or K column pair: rotate
                    const int p = (col >> 1) & 63;
                    float c0 = fc[row * 64 + p],       s0 = fs[row * 64 + p];
                    float c1 = fc[(row + 8) * 64 + p], s1 = fs[(row + 8) * 64 + p];
                    float r0 = v0 * c0 - v1 * s0, i0n = v0 * s0 + v1 * c0;
                    float r1 = v2 * c1 - v3 * s1, i1n = v2 * s1 + v3 * c1;
                    v0 = r0; v1 = i0n; v2 = r1; v3 = i1n;
                }
                *(uint32_t*)(Ch + (size_t)row * ldc + col)       = pack2h(v0, v1);
                *(uint32_t*)(Ch + (size_t)(row + 8) * ldc + col) = pack2h(v2, v3);
            } else {
                *(float2*)(Cf + (size_t)row * ldc + col) =
                    make_float2(d[mt][nt][0], d[mt][nt][1]);
                *(float2*)(Cf + (size_t)(row + 8) * ldc + col) =
                    make_float2(d[mt][nt][2], d[mt][nt][3]);
            }
        }
    }
}

// ---------------------------------------------------------------------------
// Tensor-core flash attention (fp16 operands, fp32 accum).
// Block = 128 q x 1 head, 8 warps x 16 rows.  Longest-first scheduling.
// qkv is fp16 with RoPE pre-applied -> all tile loads are cp.async.
// smem (halfs): Q[128][136] | buf0{K[64][136] V[64][136]} | buf1{K V}
// ---------------------------------------------------------------------------
#define FS     136
#define KVBUF  17408                      /* halfs per K+V buffer            */
#define FLASH_SMEM2 ((17408 + 2 * KVBUF) * 2)   /* 104448 B */

__global__ void __launch_bounds__(256, 1) flash_mma()
{
    extern __shared__ __half sb[];
    const uint32_t sb2 = smem_u32(sb);
    const int qt = (int)gridDim.x - 1 - (int)blockIdx.x;  // longest tiles first
    const int h = blockIdx.y;
    const int q0 = qt * 128;
    const int kvh = h >> 2;
    const int tid = threadIdx.x;
    const int wid = tid >> 5, lane = tid & 31;
    const int g = lane >> 2, t = lane & 3;
    const int rmin = q0 + wid * 16;
    const uint32_t LM = (lane & 15) * FS + ((lane >> 4) << 3);

    const __half* qkvh = g_qkvh;
    const int nkt = 2 * (qt + 1);

    // Q tile: 128 rows x 16 chunks of 16 B, cp.async
    const __half* qb = qkvh + (size_t)q0 * QKV_W + h * HD;
#pragma unroll
    for (int p = 0; p < 8; p++) {
        int i = tid + p * 256;
        int r = i >> 4, c8 = i & 15;
        cp_async16(sb2 + 2 * (r * FS + c8 * 8), qb + (size_t)r * QKV_W + c8 * 8);
    }

    // K/V stage loader: 64 rows x 16 chunks each
    auto kv_issue = [&](int kt, int buf) {
        const __half* kb = qkvh + (size_t)(kt * 64) * QKV_W + DIM + kvh * HD;
        const __half* vb = kb + KVD;
        const uint32_t kdst = sb2 + 2 * (17408 + buf * KVBUF);
        const uint32_t vdst = kdst + 2 * 8704;
#pragma unroll
        for (int p = 0; p < 4; p++) {
            int i = tid + p * 256;
            int r = i >> 4, c8 = i & 15;
            uint32_t o2 = 2 * (r * FS + c8 * 8);
            cp_async16(kdst + o2, kb + (size_t)r * QKV_W + c8 * 8);
            cp_async16(vdst + o2, vb + (size_t)r * QKV_W + c8 * 8);
        }
        asm volatile("cp.async.commit_group;" ::: "memory");
    };

    kv_issue(0, 0);   // group 0 = Q + KV(0)

    float m0 = -1e30f, m1 = -1e30f, l0 = 0.f, l1 = 0.f;
    float o[16][4];
#pragma unroll
    for (int i = 0; i < 16; i++)
#pragma unroll
        for (int e = 0; e < 4; e++) o[i][e] = 0.f;

    const float scale = 0.08838834764831845f;

    for (int kt = 0; kt < nkt; kt++) {
        const int buf = kt & 1;
        __syncthreads();                          // prior compute on buf^1 done
        if (kt + 1 < nkt) {
            kv_issue(kt + 1, buf ^ 1);
            asm volatile("cp.async.wait_group 1;" ::: "memory");
        } else {
            asm volatile("cp.async.wait_group 0;" ::: "memory");
        }
        __syncthreads();

        if (kt * 64 > rmin + 15) continue;        // warp fully masked: skip

        const uint32_t KHO = 17408 + buf * KVBUF;
        const uint32_t VHO = KHO + 8704;

        float s[8][4];
#pragma unroll
        for (int i = 0; i < 8; i++)
#pragma unroll
            for (int e = 0; e < 4; e++) s[i][e] = 0.f;

#pragma unroll
        for (int ks = 0; ks < 8; ks++) {
            uint32_t qa = sb2 + 2 * (wid * 16 * FS + LM + ks * 16);
            uint32_t qh0, qh1, qh2, qh3;
            ldsm4(qh0, qh1, qh2, qh3, qa);
#pragma unroll
            for (int np = 0; np < 4; np++) {
                uint32_t ka = sb2 + 2 * (KHO + np * 16 * FS + LM + ks * 16);
                uint32_t kh0, kh1, kh2, kh3;
                ldsm4(kh0, kh1, kh2, kh3, ka);
                float* se = s[2 * np];
                float* so = s[2 * np + 1];
                mma_fp16(se[0], se[1], se[2], se[3], qh0, qh1, qh2, qh3, kh0, kh2);
                mma_fp16(so[0], so[1], so[2], so[3], qh0, qh1, qh2, qh3, kh1, kh3);
            }
        }

        const bool dm = (kt * 64 + 63) > rmin;
#pragma unroll
        for (int nt = 0; nt < 8; nt++) {
            int colb = kt * 64 + nt * 8 + 2 * t;
#pragma unroll
            for (int e = 0; e < 4; e++) {
                float v = s[nt][e] * scale;
                if (dm && (colb + (e & 1)) > (rmin + g + (e >> 1) * 8)) v = -1e30f;
                s[nt][e] = v;
            }
        }

        float rm0 = -1e30f, rm1 = -1e30f;
#pragma unroll
        for (int nt = 0; nt < 8; nt++) {
            rm0 = fmaxf(rm0, fmaxf(s[nt][0], s[nt][1]));
            rm1 = fmaxf(rm1, fmaxf(s[nt][2], s[nt][3]));
        }
        rm0 = fmaxf(rm0, __shfl_xor_sync(0xffffffffu, rm0, 1));
        rm0 = fmaxf(rm0, __shfl_xor_sync(0xffffffffu, rm0, 2));
        rm1 = fmaxf(rm1, __shfl_xor_sync(0xffffffffu, rm1, 1));
        rm1 = fmaxf(rm1, __shfl_xor_sync(0xffffffffu, rm1, 2));
        float mn0 = fmaxf(m0, rm0), mn1 = fmaxf(m1, rm1);
        float a0 = __expf(m0 - mn0), a1 = __expf(m1 - mn1);
        m0 = mn0; m1 = mn1;
        float ls0 = 0.f, ls1 = 0.f;
#pragma unroll
        for (int nt = 0; nt < 8; nt++) {
            s[nt][0] = __expf(s[nt][0] - mn0);
            s[nt][1] = __expf(s[nt][1] - mn0);
            s[nt][2] = __expf(s[nt][2] - mn1);
            s[nt][3] = __expf(s[nt][3] - mn1);
            ls0 += s[nt][0] + s[nt][1];
            ls1 += s[nt][2] + s[nt][3];
        }
        ls0 += __shfl_xor_sync(0xffffffffu, ls0, 1);
        ls0 += __shfl_xor_sync(0xffffffffu, ls0, 2);
        ls1 += __shfl_xor_sync(0xffffffffu, ls1, 1);
        ls1 += __shfl_xor_sync(0xffffffffu, ls1, 2);
        l0 = l0 * a0 + ls0;
        l1 = l1 * a1 + ls1;
#pragma unroll
        for (int nt = 0; nt < 16; nt++) {
            o[nt][0] *= a0; o[nt][1] *= a0;
            o[nt][2] *= a1; o[nt][3] *= a1;
        }

        uint32_t pah[4][4];
#pragma unroll
        for (int k2 = 0; k2 < 4; k2++) {
            pah[k2][0] = pack2h(s[2 * k2][0],     s[2 * k2][1]);
            pah[k2][1] = pack2h(s[2 * k2][2],     s[2 * k2][3]);
            pah[k2][2] = pack2h(s[2 * k2 + 1][0], s[2 * k2 + 1][1]);
            pah[k2][3] = pack2h(s[2 * k2 + 1][2], s[2 * k2 + 1][3]);
        }

#pragma unroll
        for (int k2 = 0; k2 < 4; k2++) {
#pragma unroll
            for (int np = 0; np < 8; np++) {
                uint32_t va = sb2 + 2 * (VHO + k2 * 16 * FS + LM + np * 16);
                uint32_t vh0, vh1, vh2, vh3;
                ldsm4t(vh0, vh1, vh2, vh3, va);
                float* oe = o[2 * np];
                float* oo = o[2 * np + 1];
                mma_fp16(oe[0], oe[1], oe[2], oe[3],
                         pah[k2][0], pah[k2][1], pah[k2][2], pah[k2][3], vh0, vh1);
                mma_fp16(oo[0], oo[1], oo[2], oo[3],
                         pah[k2][0], pah[k2][1], pah[k2][2], pah[k2][3], vh2, vh3);
            }
        }
    }

    // epilogue: normalize, write fp16 (A-side of WO GEMM)
    float i0 = 1.f / l0, i1 = 1.f / l1;
    __half* oh0 = g_ah + (size_t)(rmin + g) * DIM + h * HD;
    __half* oh1 = g_ah + (size_t)(rmin + g + 8) * DIM + h * HD;
#pragma unroll
    for (int nt = 0; nt < 16; nt++) {
        int col = nt * 8 + 2 * t;
        *(uint32_t*)(oh0 + col) = pack2h(o[nt][0] * i0, o[nt][1] * i0);
        *(uint32_t*)(oh1 + col) = pack2h(o[nt][2] * i1, o[nt][3] * i1);
    }
}

// ---------------------------------------------------------------------------
extern "C" void kernel_launch(void* const* d_in, const int* in_sizes, int n_in,
                              void* d_out, int out_size)
{
    const float* x  = (const float*)d_in[0];
    const float* wq = (const float*)d_in[1];
    const float* wk = (const float*)d_in[2];
    const float* wv = (const float*)d_in[3];
    const float* wo = (const float*)d_in[4];
    const float* fc = (const float*)d_in[7];
    const float* fs = (const float*)d_in[8];
    float* out = (float*)d_out;
    (void)in_sizes; (void)n_in; (void)out_size;

    static __half* qkvh = nullptr;
    static __half *xh, *wAh, *woh, *ah;
    if (!qkvh) {   // first call is the uncaptured correctness run
        cudaGetSymbolAddress((void**)&qkvh, g_qkvh);
        cudaGetSymbolAddress((void**)&xh, g_xh);
        cudaGetSymbolAddress((void**)&wAh, g_wAh);
        cudaGetSymbolAddress((void**)&woh, g_woh);
        cudaGetSymbolAddress((void**)&ah, g_ah);
        cudaFuncSetAttribute(gemm_mma2<true>,
                             cudaFuncAttributeMaxDynamicSharedMemorySize, GEMM_SMEM);
        cudaFuncSetAttribute(gemm_mma2<false>,
                             cudaFuncAttributeMaxDynamicSharedMemorySize, GEMM_SMEM);
        cudaFuncSetAttribute(flash_mma,
                             cudaFuncAttributeMaxDynamicSharedMemorySize, FLASH_SMEM2);
    }

    // fp32 -> fp16 conversions (wq|wk|wv fused into one [6144 x 4096] buffer)
    conv_kernel<<<(SEQ * DIM / 4 + 255) / 256, 256>>>(x, xh, SEQ * DIM / 4);
    conv_kernel<<<(DIM * DIM / 4 + 255) / 256, 256>>>(wq, wAh, DIM * DIM / 4);
    conv_kernel<<<(KVD * DIM / 4 + 255) / 256, 256>>>(
        wk, wAh + (size_t)DIM * DIM, KVD * DIM / 4);
    conv_kernel<<<(KVD * DIM / 4 + 255) / 256, 256>>>(
        wv, wAh + (size_t)(DIM + KVD) * DIM, KVD * DIM / 4);
    conv_kernel<<<(DIM * DIM / 4 + 255) / 256, 256>>>(wo, woh, DIM * DIM / 4);

    // Fused QKV projection + RoPE -> g_qkvh [S, 6144] fp16
    gemm_mma2<true><<<dim3(QKV_W / 256, SEQ / 128), 256, GEMM_SMEM>>>(
        xh, wAh, nullptr, qkvh, fc, fs, QKV_W, DIM);

    // Causal GQA flash attention (cp.async double-buffered K/V) -> g_ah
    flash_mma<<<dim3(SEQ / 128, NH), 256, FLASH_SMEM2>>>();

    // Output projection -> fp32 out
    gemm_mma2<false><<<dim3(DIM / 256, SEQ / 128), 256, GEMM_SMEM>>>(
        ah, woh, out, nullptr, nullptr, nullptr, DIM, DIM);
}